// round 1
// baseline (speedup 1.0000x reference)
#include <cuda_runtime.h>
#include <math.h>

// Problem constants
#define BATCH 2
#define SEQL 2048
#define NTOK (BATCH * SEQL)          // 4096
#define DMODEL 512
#define ED 1024
#define DSTATE 16
#define DCONV 4
#define DTRANK 32
#define NLAYERS 2

// Scratch buffers (static device allocation — no cudaMalloc allowed)
__device__ float g_hn[NTOK * DMODEL];     // rmsnorm output
__device__ float g_xz[NTOK * 2 * ED];     // in_proj output (xi | z)
__device__ float g_xic[NTOK * ED];        // conv + silu output
__device__ float g_dbc[NTOK * 64];        // x_proj output (dt | B | C)
__device__ float g_delta[NTOK * ED];      // softplus(dt_proj)
__device__ float g_y[NTOK * ED];          // scan output, gated

// ---------------------------------------------------------------------------
// Generic tiled SGEMM:  C[M,N] (=, +=) A[M,K] @ W[N,K]^T   (+bias, +softplus)
// BM=BN=64, BK=16, 256 threads, 4x4 micro-tile per thread.
// Requires M%64==0, N%64==0, K%16==0 (true for all calls here).
// ---------------------------------------------------------------------------
template <bool BIAS, bool ACCUM, bool SOFTPLUS>
__global__ void gemm_kernel(const float* __restrict__ A, int lda,
                            const float* __restrict__ W, int ldw,
                            const float* __restrict__ bias,
                            float* __restrict__ C, int ldc,
                            int K)
{
    __shared__ float As[16][68];
    __shared__ float Ws[16][68];

    const int tx = threadIdx.x & 15;       // 0..15
    const int ty = threadIdx.x >> 4;       // 0..15
    const int m0 = blockIdx.y * 64;
    const int n0 = blockIdx.x * 64;

    float c[4][4] = {};

    for (int k0 = 0; k0 < K; k0 += 16) {
        #pragma unroll
        for (int r = 0; r < 4; r++) {
            int i = ty + 16 * r;
            As[tx][i] = A[(size_t)(m0 + i) * lda + k0 + tx];
            Ws[tx][i] = W[(size_t)(n0 + i) * ldw + k0 + tx];
        }
        __syncthreads();

        #pragma unroll
        for (int kk = 0; kk < 16; kk++) {
            float4 a = *(const float4*)&As[kk][ty * 4];
            float4 b = *(const float4*)&Ws[kk][tx * 4];
            c[0][0] = fmaf(a.x, b.x, c[0][0]); c[0][1] = fmaf(a.x, b.y, c[0][1]);
            c[0][2] = fmaf(a.x, b.z, c[0][2]); c[0][3] = fmaf(a.x, b.w, c[0][3]);
            c[1][0] = fmaf(a.y, b.x, c[1][0]); c[1][1] = fmaf(a.y, b.y, c[1][1]);
            c[1][2] = fmaf(a.y, b.z, c[1][2]); c[1][3] = fmaf(a.y, b.w, c[1][3]);
            c[2][0] = fmaf(a.z, b.x, c[2][0]); c[2][1] = fmaf(a.z, b.y, c[2][1]);
            c[2][2] = fmaf(a.z, b.z, c[2][2]); c[2][3] = fmaf(a.z, b.w, c[2][3]);
            c[3][0] = fmaf(a.w, b.x, c[3][0]); c[3][1] = fmaf(a.w, b.y, c[3][1]);
            c[3][2] = fmaf(a.w, b.z, c[3][2]); c[3][3] = fmaf(a.w, b.w, c[3][3]);
        }
        __syncthreads();
    }

    const int col = n0 + tx * 4;
    float4 bb;
    if (BIAS) bb = *(const float4*)&bias[col];

    #pragma unroll
    for (int i = 0; i < 4; i++) {
        const int row = m0 + ty * 4 + i;
        float4 v = make_float4(c[i][0], c[i][1], c[i][2], c[i][3]);
        if (BIAS) { v.x += bb.x; v.y += bb.y; v.z += bb.z; v.w += bb.w; }
        if (SOFTPLUS) {
            v.x = (v.x > 20.f) ? v.x : log1pf(__expf(v.x));
            v.y = (v.y > 20.f) ? v.y : log1pf(__expf(v.y));
            v.z = (v.z > 20.f) ? v.z : log1pf(__expf(v.z));
            v.w = (v.w > 20.f) ? v.w : log1pf(__expf(v.w));
        }
        float* cp = &C[(size_t)row * ldc + col];
        if (ACCUM) {
            float4 o = *(const float4*)cp;
            v.x += o.x; v.y += o.y; v.z += o.z; v.w += o.w;
        }
        *(float4*)cp = v;
    }
}

// ---------------------------------------------------------------------------
// RMSNorm over the last dim (512). One block per token, 256 threads.
// ---------------------------------------------------------------------------
__global__ void rmsnorm_kernel(const float* __restrict__ h,
                               const float* __restrict__ w,
                               float* __restrict__ out)
{
    const int t = blockIdx.x;
    const float* hp = h + (size_t)t * DMODEL;
    float v0 = hp[threadIdx.x];
    float v1 = hp[threadIdx.x + 256];
    float s = v0 * v0 + v1 * v1;
    #pragma unroll
    for (int o = 16; o; o >>= 1) s += __shfl_xor_sync(0xffffffffu, s, o);

    __shared__ float ws[8];
    __shared__ float rtot;
    if ((threadIdx.x & 31) == 0) ws[threadIdx.x >> 5] = s;
    __syncthreads();
    if (threadIdx.x == 0) {
        float tot = 0.f;
        #pragma unroll
        for (int i = 0; i < 8; i++) tot += ws[i];
        rtot = rsqrtf(tot / (float)DMODEL + 1e-5f);
    }
    __syncthreads();
    const float r = rtot;
    out[(size_t)t * DMODEL + threadIdx.x]       = v0 * r * w[threadIdx.x];
    out[(size_t)t * DMODEL + threadIdx.x + 256] = v1 * r * w[threadIdx.x + 256];
}

// ---------------------------------------------------------------------------
// Depthwise causal conv (kernel 4) + bias + silu. xi is cols [0,ED) of g_xz.
// One thread per (token, channel).
// ---------------------------------------------------------------------------
__global__ void conv_kernel(const float* __restrict__ xz,
                            const float* __restrict__ cw,
                            const float* __restrict__ cb,
                            float* __restrict__ out)
{
    const int idx = blockIdx.x * blockDim.x + threadIdx.x;   // over NTOK*ED
    const int e = idx & (ED - 1);
    const int tl = idx >> 10;                // b*L + t
    const int t = tl & (SEQL - 1);

    float acc = cb[e];
    #pragma unroll
    for (int k = 0; k < DCONV; k++) {
        const int tt = t - (DCONV - 1) + k;
        if (tt >= 0)
            acc = fmaf(cw[e * DCONV + k],
                       xz[(size_t)(tl - (DCONV - 1) + k) * (2 * ED) + e], acc);
    }
    out[idx] = acc / (1.f + __expf(-acc));   // silu
}

// ---------------------------------------------------------------------------
// Selective scan + output gating, fused.
// One warp handles 2 channels; lane = (group g in {0,1}) x (state n in 0..15).
// hs recurrence is a single FMA chain; y reduced over 16 states via shfl.
// y[t,e] = (sum_n hs*C + D*xi) * silu(z)
// ---------------------------------------------------------------------------
__global__ void scan_kernel(const float* __restrict__ delta,
                            const float* __restrict__ xi,
                            const float* __restrict__ dbc,
                            const float* __restrict__ xz,
                            const float* __restrict__ A_log,
                            const float* __restrict__ Dp,
                            float* __restrict__ y)
{
    const int lane = threadIdx.x & 31;
    const int warp = threadIdx.x >> 5;
    const int n = lane & 15;
    const int g = lane >> 4;
    const int c = blockIdx.x * 16 + warp * 2 + g;   // 0 .. B*ED-1
    const int b = c >> 10;
    const int e = c & (ED - 1);

    const float a  = -__expf(A_log[e * DSTATE + n]);
    const float Dv = Dp[e];

    const float* dptr  = delta + (size_t)b * SEQL * ED + e;
    const float* xptr  = xi    + (size_t)b * SEQL * ED + e;
    const float* bcptr = dbc   + (size_t)b * SEQL * 64;
    const float* zptr  = xz    + (size_t)b * SEQL * (2 * ED) + ED + e;
    float*       yptr  = y     + (size_t)b * SEQL * ED + e;

    float hs = 0.f;
    for (int t = 0; t < SEQL; t++) {
        const float dv = dptr[(size_t)t * ED];
        const float xv = xptr[(size_t)t * ED];
        const float Bn = bcptr[t * 64 + DTRANK + n];
        const float Cn = bcptr[t * 64 + DTRANK + DSTATE + n];
        const float dA = __expf(dv * a);
        hs = fmaf(dA, hs, dv * xv * Bn);
        float p = hs * Cn;
        p += __shfl_xor_sync(0xffffffffu, p, 8);
        p += __shfl_xor_sync(0xffffffffu, p, 4);
        p += __shfl_xor_sync(0xffffffffu, p, 2);
        p += __shfl_xor_sync(0xffffffffu, p, 1);
        if (n == 0) {
            const float zv = zptr[(size_t)t * (2 * ED)];
            const float silu_z = zv / (1.f + __expf(-zv));
            yptr[(size_t)t * ED] = (p + Dv * xv) * silu_z;
        }
    }
}

// ---------------------------------------------------------------------------
// Host launch
// ---------------------------------------------------------------------------
extern "C" void kernel_launch(void* const* d_in, const int* in_sizes, int n_in,
                              void* d_out, int out_size)
{
    const float* x        = (const float*)d_in[0];
    const float* emb_w    = (const float*)d_in[1];
    const float* emb_b    = (const float*)d_in[2];
    const float* in_w     = (const float*)d_in[3];
    const float* conv_w   = (const float*)d_in[4];
    const float* conv_b   = (const float*)d_in[5];
    const float* xp_w     = (const float*)d_in[6];
    const float* dt_w     = (const float*)d_in[7];
    const float* dt_b     = (const float*)d_in[8];
    const float* A_log    = (const float*)d_in[9];
    const float* Dparam   = (const float*)d_in[10];
    const float* out_w    = (const float*)d_in[11];
    const float* norm_w   = (const float*)d_in[12];
    float* h = (float*)d_out;   // residual stream lives in d_out

    float *hn, *xz, *xic, *dbc, *delta, *yb;
    cudaGetSymbolAddress((void**)&hn,    g_hn);
    cudaGetSymbolAddress((void**)&xz,    g_xz);
    cudaGetSymbolAddress((void**)&xic,   g_xic);
    cudaGetSymbolAddress((void**)&dbc,   g_dbc);
    cudaGetSymbolAddress((void**)&delta, g_delta);
    cudaGetSymbolAddress((void**)&yb,    g_y);

    const dim3 tb(256);

    // Embedding: h = x @ emb_w^T + emb_b   (M=4096, N=512, K=64)
    gemm_kernel<true, false, false><<<dim3(DMODEL / 64, NTOK / 64), tb>>>(
        x, 64, emb_w, 64, emb_b, h, DMODEL, 64);

    for (int layer = 0; layer < NLAYERS; layer++) {
        const float* l_in_w   = in_w   + (size_t)layer * 2 * ED * DMODEL;
        const float* l_conv_w = conv_w + (size_t)layer * ED * DCONV;
        const float* l_conv_b = conv_b + (size_t)layer * ED;
        const float* l_xp_w   = xp_w   + (size_t)layer * 64 * ED;
        const float* l_dt_w   = dt_w   + (size_t)layer * ED * DTRANK;
        const float* l_dt_b   = dt_b   + (size_t)layer * ED;
        const float* l_A_log  = A_log  + (size_t)layer * ED * DSTATE;
        const float* l_D      = Dparam + (size_t)layer * ED;
        const float* l_out_w  = out_w  + (size_t)layer * DMODEL * ED;
        const float* l_norm_w = norm_w + (size_t)layer * DMODEL;

        // 1. hn = rmsnorm(h)
        rmsnorm_kernel<<<NTOK, 256>>>(h, l_norm_w, hn);

        // 2. xz = hn @ in_proj^T   (M=4096, N=2048, K=512)
        gemm_kernel<false, false, false><<<dim3(2 * ED / 64, NTOK / 64), tb>>>(
            hn, DMODEL, l_in_w, DMODEL, nullptr, xz, 2 * ED, DMODEL);

        // 3. xi = silu(causal_conv(xz[:, :ED]) + cb)
        conv_kernel<<<(NTOK * ED) / 256, 256>>>(xz, l_conv_w, l_conv_b, xic);

        // 4. dbc = xi @ x_proj^T   (M=4096, N=64, K=1024)
        gemm_kernel<false, false, false><<<dim3(1, NTOK / 64), tb>>>(
            xic, ED, l_xp_w, ED, nullptr, dbc, 64, ED);

        // 5. delta = softplus(dt @ dt_proj^T + dt_b)  (M=4096, N=1024, K=32, lda=64)
        gemm_kernel<true, false, true><<<dim3(ED / 64, NTOK / 64), tb>>>(
            dbc, 64, l_dt_w, DTRANK, l_dt_b, delta, ED, DTRANK);

        // 6. scan + gating -> y
        scan_kernel<<<(BATCH * ED) / 16, 256>>>(delta, xic, dbc, xz,
                                                l_A_log, l_D, yb);

        // 7. h += y @ out_proj^T   (M=4096, N=512, K=1024)
        gemm_kernel<false, true, false><<<dim3(DMODEL / 64, NTOK / 64), tb>>>(
            yb, ED, l_out_w, ED, nullptr, h, DMODEL, ED);
    }
}

// round 3
// speedup vs baseline: 1.2804x; 1.2804x over previous
#include <cuda_runtime.h>
#include <math.h>
#include <cstdint>

// Problem constants
#define BATCH 2
#define SEQL 2048
#define NTOK (BATCH * SEQL)          // 4096
#define DMODEL 512
#define ED 1024
#define DSTATE 16
#define DCONV 4
#define DTRANK 32
#define NLAYERS 2

// Scratch buffers (no cudaMalloc allowed)
__device__ float g_hn[NTOK * DMODEL];
__device__ float g_xz[NTOK * 2 * ED];
__device__ float g_xic[NTOK * ED];
__device__ float g_dbc[NTOK * 64];
__device__ float g_delta[NTOK * ED];
__device__ float g_y[NTOK * ED];

// ---------------------------------------------------------------------------
// Small PTX helpers (baseline ISA only — no tcgen05 on compute_103 target)
// ---------------------------------------------------------------------------
__device__ __forceinline__ uint32_t smem_u32(const void* p) {
    uint32_t a;
    asm("{ .reg .u64 t; cvta.to.shared.u64 t, %1; cvt.u32.u64 %0, t; }"
        : "=r"(a) : "l"(p));
    return a;
}

__device__ __forceinline__ void cp_async16(void* smem, const void* gmem) {
    uint32_t s = smem_u32(smem);
    asm volatile("cp.async.cg.shared.global [%0], [%1], 16;"
                 :: "r"(s), "l"(gmem) : "memory");
}
#define CP_COMMIT() asm volatile("cp.async.commit_group;" ::: "memory")
#define CP_WAIT(n)  asm volatile("cp.async.wait_group %0;" :: "n"(n) : "memory")

// m16n8k8 tf32 HMMA: D += A @ B (A row-major 16x8, B col-major 8x8)
__device__ __forceinline__ void mma_tf32(float* c, const uint32_t* a,
                                         const uint32_t* b) {
    asm volatile(
        "mma.sync.aligned.m16n8k8.row.col.f32.tf32.tf32.f32 "
        "{%0,%1,%2,%3}, {%4,%5,%6,%7}, {%8,%9}, {%0,%1,%2,%3};"
        : "+f"(c[0]), "+f"(c[1]), "+f"(c[2]), "+f"(c[3])
        : "r"(a[0]), "r"(a[1]), "r"(a[2]), "r"(a[3]), "r"(b[0]), "r"(b[1]));
}

__device__ __forceinline__ float softplus_f(float v) {
    return (v > 20.f) ? v : log1pf(__expf(v));
}

// ---------------------------------------------------------------------------
// tf32 tensor-core GEMM:  C[M,N] (=, +=) A[M,K] @ W[N,K]^T  (+bias, +softplus)
// BM=128, BN=TILE_N, BK=16, 256 threads (8 warps, 4x2), warp tile 32 x TILE_N/2.
// Double-buffered cp.async pipeline. M%128==0, N%TILE_N==0, K%16==0.
// Smem row stride 20 floats -> conflict-free fragment LDS.
// ---------------------------------------------------------------------------
template <int TILE_N, bool BIAS, bool ACCUM, bool SOFTPLUS>
__global__ __launch_bounds__(256) void tgemm(
    const float* __restrict__ A, int lda,
    const float* __restrict__ W, int ldw,
    const float* __restrict__ bias,
    float* __restrict__ C, int ldc, int K)
{
    constexpr int BM = 128, BK = 16, STR = 20;
    constexpr int WN = TILE_N / 2;
    constexpr int NJ = WN / 8;

    __shared__ float sA[2][BM * STR];
    __shared__ float sB[2][TILE_N * STR];

    const int tid = threadIdx.x;
    const int wid = tid >> 5, lane = tid & 31;
    const int gid = lane >> 2, tig = lane & 3;
    const int wm = (wid >> 1) * 32;       // warp row origin in tile
    const int wn = (wid & 1) * WN;        // warp col origin in tile
    const int m0 = blockIdx.y * BM;
    const int n0 = blockIdx.x * TILE_N;

    float c[2][NJ][4] = {};

    const int KT = K / BK;

    auto load_tile = [&](int kt, int buf) {
        const int k0 = kt * BK;
        #pragma unroll
        for (int i = 0; i < (BM * 4) / 256; i++) {
            int ch = tid + 256 * i, r = ch >> 2, q = ch & 3;
            cp_async16(&sA[buf][r * STR + q * 4],
                       &A[(size_t)(m0 + r) * lda + k0 + q * 4]);
        }
        #pragma unroll
        for (int i = 0; i < (TILE_N * 4) / 256; i++) {
            int ch = tid + 256 * i, r = ch >> 2, q = ch & 3;
            cp_async16(&sB[buf][r * STR + q * 4],
                       &W[(size_t)(n0 + r) * ldw + k0 + q * 4]);
        }
        CP_COMMIT();
    };

    load_tile(0, 0);

    for (int kt = 0; kt < KT; kt++) {
        if (kt + 1 < KT) {
            load_tile(kt + 1, (kt + 1) & 1);
            CP_WAIT(1);
        } else {
            CP_WAIT(0);
        }
        __syncthreads();

        const float* bufA = sA[kt & 1];
        const float* bufB = sB[kt & 1];
        #pragma unroll
        for (int s = 0; s < 2; s++) {          // two K=8 steps per BK=16
            const int k = s * 8;
            uint32_t a[2][4], b[NJ][2];
            #pragma unroll
            for (int i = 0; i < 2; i++) {
                const float* p = &bufA[(wm + i * 16 + gid) * STR + k + tig];
                a[i][0] = __float_as_uint(p[0]);
                a[i][1] = __float_as_uint(p[8 * STR]);
                a[i][2] = __float_as_uint(p[4]);
                a[i][3] = __float_as_uint(p[8 * STR + 4]);
            }
            #pragma unroll
            for (int j = 0; j < NJ; j++) {
                const float* p = &bufB[(wn + j * 8 + gid) * STR + k + tig];
                b[j][0] = __float_as_uint(p[0]);
                b[j][1] = __float_as_uint(p[4]);
            }
            #pragma unroll
            for (int i = 0; i < 2; i++)
                #pragma unroll
                for (int j = 0; j < NJ; j++)
                    mma_tf32(c[i][j], a[i], b[j]);
        }
        __syncthreads();
    }

    // epilogue
    #pragma unroll
    for (int i = 0; i < 2; i++) {
        #pragma unroll
        for (int half = 0; half < 2; half++) {
            const int row = m0 + wm + i * 16 + gid + half * 8;
            #pragma unroll
            for (int j = 0; j < NJ; j++) {
                const int col = n0 + wn + j * 8 + tig * 2;
                float vx = c[i][j][half * 2 + 0];
                float vy = c[i][j][half * 2 + 1];
                if (BIAS) {
                    float2 bb = *(const float2*)&bias[col];
                    vx += bb.x; vy += bb.y;
                }
                if (SOFTPLUS) { vx = softplus_f(vx); vy = softplus_f(vy); }
                float* cp = &C[(size_t)row * ldc + col];
                if (ACCUM) {
                    float2 o = *(const float2*)cp;
                    vx += o.x; vy += o.y;
                }
                *(float2*)cp = make_float2(vx, vy);
            }
        }
    }
}

// ---------------------------------------------------------------------------
// RMSNorm over last dim (512). One block per token.
// ---------------------------------------------------------------------------
__global__ void rmsnorm_kernel(const float* __restrict__ h,
                               const float* __restrict__ w,
                               float* __restrict__ out)
{
    const int t = blockIdx.x;
    const float* hp = h + (size_t)t * DMODEL;
    float v0 = hp[threadIdx.x];
    float v1 = hp[threadIdx.x + 256];
    float s = v0 * v0 + v1 * v1;
    #pragma unroll
    for (int o = 16; o; o >>= 1) s += __shfl_xor_sync(0xffffffffu, s, o);

    __shared__ float ws[8];
    __shared__ float rtot;
    if ((threadIdx.x & 31) == 0) ws[threadIdx.x >> 5] = s;
    __syncthreads();
    if (threadIdx.x == 0) {
        float tot = 0.f;
        #pragma unroll
        for (int i = 0; i < 8; i++) tot += ws[i];
        rtot = rsqrtf(tot / (float)DMODEL + 1e-5f);
    }
    __syncthreads();
    const float r = rtot;
    out[(size_t)t * DMODEL + threadIdx.x]       = v0 * r * w[threadIdx.x];
    out[(size_t)t * DMODEL + threadIdx.x + 256] = v1 * r * w[threadIdx.x + 256];
}

// ---------------------------------------------------------------------------
// Depthwise causal conv (k=4) + bias + silu on xi = xz[:, :ED].
// ---------------------------------------------------------------------------
__global__ void conv_kernel(const float* __restrict__ xz,
                            const float* __restrict__ cw,
                            const float* __restrict__ cb,
                            float* __restrict__ out)
{
    const int idx = blockIdx.x * blockDim.x + threadIdx.x;
    const int e = idx & (ED - 1);
    const int tl = idx >> 10;
    const int t = tl & (SEQL - 1);

    float acc = cb[e];
    #pragma unroll
    for (int k = 0; k < DCONV; k++) {
        const int tt = t - (DCONV - 1) + k;
        if (tt >= 0)
            acc = fmaf(cw[e * DCONV + k],
                       xz[(size_t)(tl - (DCONV - 1) + k) * (2 * ED) + e], acc);
    }
    out[idx] = acc / (1.f + __expf(-acc));
}

// ---------------------------------------------------------------------------
// Selective scan + gating. One warp = 2 channels x 16 states.
// ---------------------------------------------------------------------------
__global__ void scan_kernel(const float* __restrict__ delta,
                            const float* __restrict__ xi,
                            const float* __restrict__ dbc,
                            const float* __restrict__ xz,
                            const float* __restrict__ A_log,
                            const float* __restrict__ Dp,
                            float* __restrict__ y)
{
    const int lane = threadIdx.x & 31;
    const int warp = threadIdx.x >> 5;
    const int n = lane & 15;
    const int g = lane >> 4;
    const int c = blockIdx.x * 16 + warp * 2 + g;
    const int b = c >> 10;
    const int e = c & (ED - 1);

    const float a  = -__expf(A_log[e * DSTATE + n]);
    const float Dv = Dp[e];

    const float* dptr  = delta + (size_t)b * SEQL * ED + e;
    const float* xptr  = xi    + (size_t)b * SEQL * ED + e;
    const float* bcptr = dbc   + (size_t)b * SEQL * 64;
    const float* zptr  = xz    + (size_t)b * SEQL * (2 * ED) + ED + e;
    float*       yptr  = y     + (size_t)b * SEQL * ED + e;

    float hs = 0.f;
    for (int t = 0; t < SEQL; t++) {
        const float dv = dptr[(size_t)t * ED];
        const float xv = xptr[(size_t)t * ED];
        const float Bn = bcptr[t * 64 + DTRANK + n];
        const float Cn = bcptr[t * 64 + DTRANK + DSTATE + n];
        const float dA = __expf(dv * a);
        hs = fmaf(dA, hs, dv * xv * Bn);
        float p = hs * Cn;
        p += __shfl_xor_sync(0xffffffffu, p, 8);
        p += __shfl_xor_sync(0xffffffffu, p, 4);
        p += __shfl_xor_sync(0xffffffffu, p, 2);
        p += __shfl_xor_sync(0xffffffffu, p, 1);
        if (n == 0) {
            const float zv = zptr[(size_t)t * (2 * ED)];
            const float silu_z = zv / (1.f + __expf(-zv));
            yptr[(size_t)t * ED] = (p + Dv * xv) * silu_z;
        }
    }
}

// ---------------------------------------------------------------------------
// Host launch
// ---------------------------------------------------------------------------
extern "C" void kernel_launch(void* const* d_in, const int* in_sizes, int n_in,
                              void* d_out, int out_size)
{
    const float* x        = (const float*)d_in[0];
    const float* emb_w    = (const float*)d_in[1];
    const float* emb_b    = (const float*)d_in[2];
    const float* in_w     = (const float*)d_in[3];
    const float* conv_w   = (const float*)d_in[4];
    const float* conv_b   = (const float*)d_in[5];
    const float* xp_w     = (const float*)d_in[6];
    const float* dt_w     = (const float*)d_in[7];
    const float* dt_b     = (const float*)d_in[8];
    const float* A_log    = (const float*)d_in[9];
    const float* Dparam   = (const float*)d_in[10];
    const float* out_w    = (const float*)d_in[11];
    const float* norm_w   = (const float*)d_in[12];
    float* h = (float*)d_out;

    float *hn, *xz, *xic, *dbc, *delta, *yb;
    cudaGetSymbolAddress((void**)&hn,    g_hn);
    cudaGetSymbolAddress((void**)&xz,    g_xz);
    cudaGetSymbolAddress((void**)&xic,   g_xic);
    cudaGetSymbolAddress((void**)&dbc,   g_dbc);
    cudaGetSymbolAddress((void**)&delta, g_delta);
    cudaGetSymbolAddress((void**)&yb,    g_y);

    // Embedding: h = x @ emb_w^T + emb_b  (M=4096, N=512, K=64)
    tgemm<128, true, false, false><<<dim3(DMODEL / 128, NTOK / 128), 256>>>(
        x, 64, emb_w, 64, emb_b, h, DMODEL, 64);

    for (int layer = 0; layer < NLAYERS; layer++) {
        const float* l_in_w   = in_w   + (size_t)layer * 2 * ED * DMODEL;
        const float* l_conv_w = conv_w + (size_t)layer * ED * DCONV;
        const float* l_conv_b = conv_b + (size_t)layer * ED;
        const float* l_xp_w   = xp_w   + (size_t)layer * 64 * ED;
        const float* l_dt_w   = dt_w   + (size_t)layer * ED * DTRANK;
        const float* l_dt_b   = dt_b   + (size_t)layer * ED;
        const float* l_A_log  = A_log  + (size_t)layer * ED * DSTATE;
        const float* l_D      = Dparam + (size_t)layer * ED;
        const float* l_out_w  = out_w  + (size_t)layer * DMODEL * ED;
        const float* l_norm_w = norm_w + (size_t)layer * DMODEL;

        // 1. hn = rmsnorm(h)
        rmsnorm_kernel<<<NTOK, 256>>>(h, l_norm_w, hn);

        // 2. xz = hn @ in_proj^T  (M=4096, N=2048, K=512)
        tgemm<128, false, false, false><<<dim3(2 * ED / 128, NTOK / 128), 256>>>(
            hn, DMODEL, l_in_w, DMODEL, nullptr, xz, 2 * ED, DMODEL);

        // 3. xi = silu(conv(xz[:, :ED]) + cb)
        conv_kernel<<<(NTOK * ED) / 256, 256>>>(xz, l_conv_w, l_conv_b, xic);

        // 4. dbc = xi @ x_proj^T  (M=4096, N=64, K=1024)
        tgemm<64, false, false, false><<<dim3(1, NTOK / 128), 256>>>(
            xic, ED, l_xp_w, ED, nullptr, dbc, 64, ED);

        // 5. delta = softplus(dbc[:, :32] @ dt_proj^T + dt_b)  (M=4096, N=1024, K=32)
        tgemm<128, true, false, true><<<dim3(ED / 128, NTOK / 128), 256>>>(
            dbc, 64, l_dt_w, DTRANK, l_dt_b, delta, ED, DTRANK);

        // 6. scan + gating -> y
        scan_kernel<<<(BATCH * ED) / 16, 256>>>(delta, xic, dbc, xz,
                                                l_A_log, l_D, yb);

        // 7. h += y @ out_proj^T  (M=4096, N=512, K=1024)
        tgemm<128, false, true, false><<<dim3(DMODEL / 128, NTOK / 128), 256>>>(
            yb, ED, l_out_w, ED, nullptr, h, DMODEL, ED);
    }
}

// round 4
// speedup vs baseline: 1.6079x; 1.2558x over previous
#include <cuda_runtime.h>
#include <math.h>
#include <cstdint>

// Problem constants
#define BATCH 2
#define SEQL 2048
#define NTOK (BATCH * SEQL)          // 4096
#define DMODEL 512
#define ED 1024
#define DSTATE 16
#define DCONV 4
#define DTRANK 32
#define NLAYERS 2

// Scratch buffers (no cudaMalloc allowed)
__device__ float g_hn[NTOK * DMODEL];
__device__ float g_xz[NTOK * 2 * ED];
__device__ float g_xic[NTOK * ED];
__device__ float g_dbc[NTOK * 64];
__device__ float g_delta[NTOK * ED];
__device__ float g_y[NTOK * ED];

__device__ __forceinline__ float softplus_f(float v) {
    return (v > 20.f) ? v : log1pf(__expf(v));
}

// ---------------------------------------------------------------------------
// fp32 FFMA GEMM:  C[M,N] (=, +=) A[M,K] @ W[N,K]^T  (+bias, +softplus)
// BM=128, BN=TILE_N (128 or 64), BK=8, 256 threads.
// Smem tiles stored k-major: sA[k][m], sB[k][n] (plane stride 132 floats,
// conflict-free transpose STS and broadcast/2-way LDS.128 fragment reads).
// Register-staged LDG double buffer, one __syncthreads per k-tile.
// Warp grid 4x2; lane grid 4(ly) x 8(lx); thread tile 8 x (TILE_N/16).
// Requires M%128==0, N%TILE_N==0, K%8==0, lda/ldw/ldc %4==0.
// ---------------------------------------------------------------------------
template <int TILE_N, bool BIAS, bool ACCUM, bool SOFTPLUS>
__global__ __launch_bounds__(256) void fgemm(
    const float* __restrict__ A, int lda,
    const float* __restrict__ W, int ldw,
    const float* __restrict__ bias,
    float* __restrict__ C, int ldc, int K)
{
    constexpr int BK = 8, ST = 132;
    constexpr int TC = TILE_N / 16;          // thread tile cols: 8 or 4
    constexpr int NBTH = TILE_N * 2;         // threads loading B tile

    __shared__ float sA[2][BK * ST];
    __shared__ float sB[2][BK * ST];

    const int tid = threadIdx.x;
    const int wid = tid >> 5, lane = tid & 31;
    const int ly = lane >> 3, lx = lane & 7;
    const int wy = wid >> 1, wx = wid & 1;
    const int rb = wy * 32 + ly * 8;                  // row base in tile
    const int cb = wx * (TILE_N / 2) + lx * TC;       // col base in tile
    const int m0 = blockIdx.y * 128;
    const int n0 = blockIdx.x * TILE_N;

    // tile-load indices
    const int arow = tid >> 1, akq = tid & 1;         // A: 256 threads
    const int brow = (tid & (NBTH - 1)) >> 1, bkq = tid & 1;
    const bool bact = (NBTH == 256) || (tid < NBTH);

    float c[8][TC] = {};
    const int KT = K / BK;

    float4 va, vb;
    // prologue LDG (kt = 0)
    va = *(const float4*)&A[(size_t)(m0 + arow) * lda + akq * 4];
    if (bact) vb = *(const float4*)&W[(size_t)(n0 + brow) * ldw + bkq * 4];

    for (int kt = 0; kt < KT; kt++) {
        const int buf = kt & 1;
        // transpose STS (conflict-free per analysis)
        {
            float* dst = &sA[buf][(akq * 4) * ST + arow];
            dst[0] = va.x; dst[ST] = va.y; dst[2 * ST] = va.z; dst[3 * ST] = va.w;
        }
        if (bact) {
            float* dst = &sB[buf][(bkq * 4) * ST + brow];
            dst[0] = vb.x; dst[ST] = vb.y; dst[2 * ST] = vb.z; dst[3 * ST] = vb.w;
        }
        __syncthreads();

        if (kt + 1 < KT) {       // overlap next LDG with compute
            const int k0 = (kt + 1) * BK;
            va = *(const float4*)&A[(size_t)(m0 + arow) * lda + k0 + akq * 4];
            if (bact) vb = *(const float4*)&W[(size_t)(n0 + brow) * ldw + k0 + bkq * 4];
        }

        const float* bufA = sA[buf];
        const float* bufB = sB[buf];
        #pragma unroll
        for (int k = 0; k < BK; k++) {
            float4 a0 = *(const float4*)&bufA[k * ST + rb];
            float4 a1 = *(const float4*)&bufA[k * ST + rb + 4];
            float4 b0 = *(const float4*)&bufB[k * ST + cb];
            float4 b1;
            if (TC == 8) b1 = *(const float4*)&bufB[k * ST + cb + 4];
            const float ar[8] = {a0.x, a0.y, a0.z, a0.w, a1.x, a1.y, a1.z, a1.w};
            const float br[8] = {b0.x, b0.y, b0.z, b0.w,
                                 (TC == 8) ? b1.x : 0.f, (TC == 8) ? b1.y : 0.f,
                                 (TC == 8) ? b1.z : 0.f, (TC == 8) ? b1.w : 0.f};
            #pragma unroll
            for (int i = 0; i < 8; i++)
                #pragma unroll
                for (int j = 0; j < TC; j++)
                    c[i][j] = fmaf(ar[i], br[j], c[i][j]);
        }
        // next iteration's __syncthreads (after its STS) protects buffer reuse
    }

    // epilogue
    float bias_r[TC];
    if (BIAS) {
        #pragma unroll
        for (int j = 0; j < TC; j++) bias_r[j] = bias[n0 + cb + j];
    }
    #pragma unroll
    for (int i = 0; i < 8; i++) {
        const int row = m0 + rb + i;
        float* cp = &C[(size_t)row * ldc + n0 + cb];
        #pragma unroll
        for (int j4 = 0; j4 < TC / 4; j4++) {
            float4 v = make_float4(c[i][j4 * 4 + 0], c[i][j4 * 4 + 1],
                                   c[i][j4 * 4 + 2], c[i][j4 * 4 + 3]);
            if (BIAS) {
                v.x += bias_r[j4 * 4 + 0]; v.y += bias_r[j4 * 4 + 1];
                v.z += bias_r[j4 * 4 + 2]; v.w += bias_r[j4 * 4 + 3];
            }
            if (SOFTPLUS) {
                v.x = softplus_f(v.x); v.y = softplus_f(v.y);
                v.z = softplus_f(v.z); v.w = softplus_f(v.w);
            }
            if (ACCUM) {
                float4 o = *(const float4*)&cp[j4 * 4];
                v.x += o.x; v.y += o.y; v.z += o.z; v.w += o.w;
            }
            *(float4*)&cp[j4 * 4] = v;
        }
    }
}

// ---------------------------------------------------------------------------
// RMSNorm over last dim (512). One block per token.
// ---------------------------------------------------------------------------
__global__ void rmsnorm_kernel(const float* __restrict__ h,
                               const float* __restrict__ w,
                               float* __restrict__ out)
{
    const int t = blockIdx.x;
    const float* hp = h + (size_t)t * DMODEL;
    float v0 = hp[threadIdx.x];
    float v1 = hp[threadIdx.x + 256];
    float s = v0 * v0 + v1 * v1;
    #pragma unroll
    for (int o = 16; o; o >>= 1) s += __shfl_xor_sync(0xffffffffu, s, o);

    __shared__ float ws[8];
    __shared__ float rtot;
    if ((threadIdx.x & 31) == 0) ws[threadIdx.x >> 5] = s;
    __syncthreads();
    if (threadIdx.x == 0) {
        float tot = 0.f;
        #pragma unroll
        for (int i = 0; i < 8; i++) tot += ws[i];
        rtot = rsqrtf(tot / (float)DMODEL + 1e-5f);
    }
    __syncthreads();
    const float r = rtot;
    out[(size_t)t * DMODEL + threadIdx.x]       = v0 * r * w[threadIdx.x];
    out[(size_t)t * DMODEL + threadIdx.x + 256] = v1 * r * w[threadIdx.x + 256];
}

// ---------------------------------------------------------------------------
// Depthwise causal conv (k=4) + bias + silu on xi = xz[:, :ED].
// ---------------------------------------------------------------------------
__global__ void conv_kernel(const float* __restrict__ xz,
                            const float* __restrict__ cw,
                            const float* __restrict__ cb,
                            float* __restrict__ out)
{
    const int idx = blockIdx.x * blockDim.x + threadIdx.x;
    const int e = idx & (ED - 1);
    const int tl = idx >> 10;
    const int t = tl & (SEQL - 1);

    float acc = cb[e];
    #pragma unroll
    for (int k = 0; k < DCONV; k++) {
        const int tt = t - (DCONV - 1) + k;
        if (tt >= 0)
            acc = fmaf(cw[e * DCONV + k],
                       xz[(size_t)(tl - (DCONV - 1) + k) * (2 * ED) + e], acc);
    }
    out[idx] = acc / (1.f + __expf(-acc));
}

// ---------------------------------------------------------------------------
// Selective scan + gating. One warp = 2 channels x 16 states.
// Software-pipelined: next iteration's loads issued before compute.
// ---------------------------------------------------------------------------
__global__ void scan_kernel(const float* __restrict__ delta,
                            const float* __restrict__ xi,
                            const float* __restrict__ dbc,
                            const float* __restrict__ xz,
                            const float* __restrict__ A_log,
                            const float* __restrict__ Dp,
                            float* __restrict__ y)
{
    const int lane = threadIdx.x & 31;
    const int warp = threadIdx.x >> 5;
    const int n = lane & 15;
    const int g = lane >> 4;
    const int c = blockIdx.x * 16 + warp * 2 + g;
    const int b = c >> 10;
    const int e = c & (ED - 1);

    const float a  = -__expf(A_log[e * DSTATE + n]);
    const float Dv = Dp[e];

    const float* dptr  = delta + (size_t)b * SEQL * ED + e;
    const float* xptr  = xi    + (size_t)b * SEQL * ED + e;
    const float* bcptr = dbc   + (size_t)b * SEQL * 64;
    const float* zptr  = xz    + (size_t)b * SEQL * (2 * ED) + ED + e;
    float*       yptr  = y     + (size_t)b * SEQL * ED + e;

    float hs = 0.f;
    float dv = __ldg(&dptr[0]);
    float xv = __ldg(&xptr[0]);
    float Bn = __ldg(&bcptr[DTRANK + n]);
    float Cn = __ldg(&bcptr[DTRANK + DSTATE + n]);
    float zv = __ldg(&zptr[0]);

    for (int t = 0; t < SEQL; t++) {
        float dv_n, xv_n, Bn_n, Cn_n, zv_n;
        if (t + 1 < SEQL) {
            dv_n = __ldg(&dptr[(size_t)(t + 1) * ED]);
            xv_n = __ldg(&xptr[(size_t)(t + 1) * ED]);
            Bn_n = __ldg(&bcptr[(t + 1) * 64 + DTRANK + n]);
            Cn_n = __ldg(&bcptr[(t + 1) * 64 + DTRANK + DSTATE + n]);
            zv_n = __ldg(&zptr[(size_t)(t + 1) * (2 * ED)]);
        }
        const float dA = __expf(dv * a);
        hs = fmaf(dA, hs, dv * xv * Bn);
        float p = hs * Cn;
        p += __shfl_xor_sync(0xffffffffu, p, 8);
        p += __shfl_xor_sync(0xffffffffu, p, 4);
        p += __shfl_xor_sync(0xffffffffu, p, 2);
        p += __shfl_xor_sync(0xffffffffu, p, 1);
        if (n == 0) {
            const float silu_z = zv / (1.f + __expf(-zv));
            yptr[(size_t)t * ED] = (p + Dv * xv) * silu_z;
        }
        dv = dv_n; xv = xv_n; Bn = Bn_n; Cn = Cn_n; zv = zv_n;
    }
}

// ---------------------------------------------------------------------------
// Host launch
// ---------------------------------------------------------------------------
extern "C" void kernel_launch(void* const* d_in, const int* in_sizes, int n_in,
                              void* d_out, int out_size)
{
    const float* x        = (const float*)d_in[0];
    const float* emb_w    = (const float*)d_in[1];
    const float* emb_b    = (const float*)d_in[2];
    const float* in_w     = (const float*)d_in[3];
    const float* conv_w   = (const float*)d_in[4];
    const float* conv_b   = (const float*)d_in[5];
    const float* xp_w     = (const float*)d_in[6];
    const float* dt_w     = (const float*)d_in[7];
    const float* dt_b     = (const float*)d_in[8];
    const float* A_log    = (const float*)d_in[9];
    const float* Dparam   = (const float*)d_in[10];
    const float* out_w    = (const float*)d_in[11];
    const float* norm_w   = (const float*)d_in[12];
    float* h = (float*)d_out;

    float *hn, *xz, *xic, *dbc, *delta, *yb;
    cudaGetSymbolAddress((void**)&hn,    g_hn);
    cudaGetSymbolAddress((void**)&xz,    g_xz);
    cudaGetSymbolAddress((void**)&xic,   g_xic);
    cudaGetSymbolAddress((void**)&dbc,   g_dbc);
    cudaGetSymbolAddress((void**)&delta, g_delta);
    cudaGetSymbolAddress((void**)&yb,    g_y);

    // Embedding: h = x @ emb_w^T + emb_b  (M=4096, N=512, K=64)
    fgemm<128, true, false, false><<<dim3(DMODEL / 128, NTOK / 128), 256>>>(
        x, 64, emb_w, 64, emb_b, h, DMODEL, 64);

    for (int layer = 0; layer < NLAYERS; layer++) {
        const float* l_in_w   = in_w   + (size_t)layer * 2 * ED * DMODEL;
        const float* l_conv_w = conv_w + (size_t)layer * ED * DCONV;
        const float* l_conv_b = conv_b + (size_t)layer * ED;
        const float* l_xp_w   = xp_w   + (size_t)layer * 64 * ED;
        const float* l_dt_w   = dt_w   + (size_t)layer * ED * DTRANK;
        const float* l_dt_b   = dt_b   + (size_t)layer * ED;
        const float* l_A_log  = A_log  + (size_t)layer * ED * DSTATE;
        const float* l_D      = Dparam + (size_t)layer * ED;
        const float* l_out_w  = out_w  + (size_t)layer * DMODEL * ED;
        const float* l_norm_w = norm_w + (size_t)layer * DMODEL;

        // 1. hn = rmsnorm(h)
        rmsnorm_kernel<<<NTOK, 256>>>(h, l_norm_w, hn);

        // 2. xz = hn @ in_proj^T  (M=4096, N=2048, K=512)
        fgemm<128, false, false, false><<<dim3(2 * ED / 128, NTOK / 128), 256>>>(
            hn, DMODEL, l_in_w, DMODEL, nullptr, xz, 2 * ED, DMODEL);

        // 3. xi = silu(conv(xz[:, :ED]) + cb)
        conv_kernel<<<(NTOK * ED) / 256, 256>>>(xz, l_conv_w, l_conv_b, xic);

        // 4. dbc = xi @ x_proj^T  (M=4096, N=64, K=1024)
        fgemm<64, false, false, false><<<dim3(1, NTOK / 128), 256>>>(
            xic, ED, l_xp_w, ED, nullptr, dbc, 64, ED);

        // 5. delta = softplus(dbc[:, :32] @ dt_proj^T + dt_b)  (M=4096, N=1024, K=32)
        fgemm<128, true, false, true><<<dim3(ED / 128, NTOK / 128), 256>>>(
            dbc, 64, l_dt_w, DTRANK, l_dt_b, delta, ED, DTRANK);

        // 6. scan + gating -> y
        scan_kernel<<<(BATCH * ED) / 16, 256>>>(delta, xic, dbc, xz,
                                                l_A_log, l_D, yb);

        // 7. h += y @ out_proj^T  (M=4096, N=512, K=1024)
        fgemm<128, false, true, false><<<dim3(DMODEL / 128, NTOK / 128), 256>>>(
            yb, ED, l_out_w, ED, nullptr, h, DMODEL, ED);
    }
}

// round 5
// speedup vs baseline: 2.4424x; 1.5190x over previous
#include <cuda_runtime.h>
#include <math.h>
#include <cstdint>

// Problem constants
#define BATCH 2
#define SEQL 2048
#define NTOK (BATCH * SEQL)          // 4096
#define DMODEL 512
#define ED 1024
#define DSTATE 16
#define DCONV 4
#define DTRANK 32
#define NLAYERS 2

// Scratch buffers (no cudaMalloc allowed)
__device__ float g_hn[NTOK * DMODEL];
__device__ float g_xz[NTOK * 2 * ED];
__device__ float g_xic[NTOK * ED];
__device__ float g_dbc[NTOK * 64];
__device__ float g_delta[NTOK * ED];
__device__ float g_y[NTOK * ED];

__device__ __forceinline__ float softplus_f(float v) {
    return (v > 20.f) ? v : log1pf(__expf(v));
}

// ---------------------------------------------------------------------------
// Packed fp32 helpers (Blackwell f32x2 — PTX baseline for sm_100 family)
// ---------------------------------------------------------------------------
typedef unsigned long long u64t;

__device__ __forceinline__ u64t dup2f(float v) {
    u64t r; unsigned u = __float_as_uint(v);
    asm("mov.b64 %0, {%1, %1};" : "=l"(r) : "r"(u));
    return r;
}
__device__ __forceinline__ void ffma2(u64t& c, u64t a, u64t b) {
    asm("fma.rn.f32x2 %0, %1, %2, %0;" : "+l"(c) : "l"(a), "l"(b));
}
__device__ __forceinline__ float2 unpack2(u64t p) {
    unsigned lo, hi;
    asm("mov.b64 {%0, %1}, %2;" : "=r"(lo), "=r"(hi) : "l"(p));
    return make_float2(__uint_as_float(lo), __uint_as_float(hi));
}

// ---------------------------------------------------------------------------
// fp32 FFMA2 GEMM:  C[M,N] (=, +=) A[M,K] @ W[N,K]^T  (+bias, +softplus)
// BM=128, BN=TILE_N (128 or 64), BK=8, 256 threads.
// Smem k-major (sX[k][m], stride 132), register-staged LDG double buffer.
// Accumulators packed in pairs along M (f32x2); A fragment pairs come free
// from LDS.128, B values are dup'd per k-step.
// ---------------------------------------------------------------------------
template <int TILE_N, bool BIAS, bool ACCUM, bool SOFTPLUS>
__global__ __launch_bounds__(256) void fgemm(
    const float* __restrict__ A, int lda,
    const float* __restrict__ W, int ldw,
    const float* __restrict__ bias,
    float* __restrict__ C, int ldc, int K)
{
    constexpr int BK = 8, ST = 132;
    constexpr int TC = TILE_N / 16;          // thread tile cols: 8 or 4
    constexpr int NBTH = TILE_N * 2;         // threads loading B tile

    __shared__ float sA[2][BK * ST];
    __shared__ float sB[2][BK * ST];

    const int tid = threadIdx.x;
    const int wid = tid >> 5, lane = tid & 31;
    const int ly = lane >> 3, lx = lane & 7;
    const int wy = wid >> 1, wx = wid & 1;
    const int rb = wy * 32 + ly * 8;                  // row base in tile
    const int cb = wx * (TILE_N / 2) + lx * TC;       // col base in tile
    const int m0 = blockIdx.y * 128;
    const int n0 = blockIdx.x * TILE_N;

    const int arow = tid >> 1, akq = tid & 1;
    const int brow = (tid & (NBTH - 1)) >> 1, bkq = tid & 1;
    const bool bact = (NBTH == 256) || (tid < NBTH);

    u64t cpk[4][TC] = {};                     // packed rows (2ih, 2ih+1)
    const int KT = K / BK;

    float4 va, vb;
    va = *(const float4*)&A[(size_t)(m0 + arow) * lda + akq * 4];
    if (bact) vb = *(const float4*)&W[(size_t)(n0 + brow) * ldw + bkq * 4];

    for (int kt = 0; kt < KT; kt++) {
        const int buf = kt & 1;
        {
            float* dst = &sA[buf][(akq * 4) * ST + arow];
            dst[0] = va.x; dst[ST] = va.y; dst[2 * ST] = va.z; dst[3 * ST] = va.w;
        }
        if (bact) {
            float* dst = &sB[buf][(bkq * 4) * ST + brow];
            dst[0] = vb.x; dst[ST] = vb.y; dst[2 * ST] = vb.z; dst[3 * ST] = vb.w;
        }
        __syncthreads();

        if (kt + 1 < KT) {
            const int k0 = (kt + 1) * BK;
            va = *(const float4*)&A[(size_t)(m0 + arow) * lda + k0 + akq * 4];
            if (bact) vb = *(const float4*)&W[(size_t)(n0 + brow) * ldw + k0 + bkq * 4];
        }

        const float* bufA = sA[buf];
        const float* bufB = sB[buf];
        #pragma unroll
        for (int k = 0; k < BK; k++) {
            const ulonglong2 a0 = *(const ulonglong2*)&bufA[k * ST + rb];
            const ulonglong2 a1 = *(const ulonglong2*)&bufA[k * ST + rb + 4];
            const u64t ap[4] = {a0.x, a0.y, a1.x, a1.y};
            float4 b0 = *(const float4*)&bufB[k * ST + cb];
            float4 b1;
            if (TC == 8) b1 = *(const float4*)&bufB[k * ST + cb + 4];
            u64t bd[TC];
            bd[0] = dup2f(b0.x); bd[1] = dup2f(b0.y);
            bd[2] = dup2f(b0.z); bd[3] = dup2f(b0.w);
            if (TC == 8) {
                bd[4] = dup2f(b1.x); bd[5] = dup2f(b1.y);
                bd[6] = dup2f(b1.z); bd[7] = dup2f(b1.w);
            }
            #pragma unroll
            for (int ih = 0; ih < 4; ih++)
                #pragma unroll
                for (int j = 0; j < TC; j++)
                    ffma2(cpk[ih][j], ap[ih], bd[j]);
        }
    }

    // epilogue
    float bias_r[TC];
    if (BIAS) {
        #pragma unroll
        for (int j = 0; j < TC; j++) bias_r[j] = bias[n0 + cb + j];
    }
    #pragma unroll
    for (int ih = 0; ih < 4; ih++) {
        float lo[TC], hi[TC];
        #pragma unroll
        for (int j = 0; j < TC; j++) {
            float2 f = unpack2(cpk[ih][j]);
            lo[j] = f.x; hi[j] = f.y;
        }
        #pragma unroll
        for (int half = 0; half < 2; half++) {
            const float* src = half ? hi : lo;
            const int row = m0 + rb + 2 * ih + half;
            float* cp = &C[(size_t)row * ldc + n0 + cb];
            #pragma unroll
            for (int j4 = 0; j4 < TC / 4; j4++) {
                float4 v = make_float4(src[j4 * 4 + 0], src[j4 * 4 + 1],
                                       src[j4 * 4 + 2], src[j4 * 4 + 3]);
                if (BIAS) {
                    v.x += bias_r[j4 * 4 + 0]; v.y += bias_r[j4 * 4 + 1];
                    v.z += bias_r[j4 * 4 + 2]; v.w += bias_r[j4 * 4 + 3];
                }
                if (SOFTPLUS) {
                    v.x = softplus_f(v.x); v.y = softplus_f(v.y);
                    v.z = softplus_f(v.z); v.w = softplus_f(v.w);
                }
                if (ACCUM) {
                    float4 o = *(const float4*)&cp[j4 * 4];
                    v.x += o.x; v.y += o.y; v.z += o.z; v.w += o.w;
                }
                *(float4*)&cp[j4 * 4] = v;
            }
        }
    }
}

// ---------------------------------------------------------------------------
// Small-M GEMM for x_proj (M=4096, N=64, K=1024): BM=32, BN=64, BK=8,
// 256 threads -> grid (1, 128) fills the chip. Thread tile 2x4 (one m-pair).
// ---------------------------------------------------------------------------
__global__ __launch_bounds__(256) void fgemm32(
    const float* __restrict__ A, int lda,
    const float* __restrict__ W, int ldw,
    float* __restrict__ C, int ldc, int K)
{
    constexpr int BK = 8, STA = 36, STB = 68;

    __shared__ float sA[2][BK * STA];
    __shared__ float sB[2][BK * STB];

    const int tid = threadIdx.x;
    const int wid = tid >> 5, lane = tid & 31;
    const int ly = lane >> 3, lx = lane & 7;
    const int wy = wid >> 1, wx = wid & 1;
    const int rb = wy * 8 + ly * 2;
    const int cb = wx * 32 + lx * 4;
    const int m0 = blockIdx.y * 32;
    const int n0 = 0;

    const int arow = tid >> 3, ak = tid & 7;          // A: 1 float/thread
    const int brow = tid >> 2, bk2 = (tid & 3) * 2;   // B: float2/thread

    u64t cpk[4] = {};
    const int KT = K / BK;

    float va;
    float2 vb;
    va = A[(size_t)(m0 + arow) * lda + ak];
    vb = *(const float2*)&W[(size_t)(n0 + brow) * ldw + bk2];

    for (int kt = 0; kt < KT; kt++) {
        const int buf = kt & 1;
        sA[buf][ak * STA + arow] = va;
        sB[buf][bk2 * STB + brow] = vb.x;
        sB[buf][(bk2 + 1) * STB + brow] = vb.y;
        __syncthreads();

        if (kt + 1 < KT) {
            const int k0 = (kt + 1) * BK;
            va = A[(size_t)(m0 + arow) * lda + k0 + ak];
            vb = *(const float2*)&W[(size_t)(n0 + brow) * ldw + k0 + bk2];
        }

        const float* bufA = sA[buf];
        const float* bufB = sB[buf];
        #pragma unroll
        for (int k = 0; k < BK; k++) {
            const u64t ap = *(const u64t*)&bufA[k * STA + rb];
            float4 b0 = *(const float4*)&bufB[k * STB + cb];
            ffma2(cpk[0], ap, dup2f(b0.x));
            ffma2(cpk[1], ap, dup2f(b0.y));
            ffma2(cpk[2], ap, dup2f(b0.z));
            ffma2(cpk[3], ap, dup2f(b0.w));
        }
    }

    float lo[4], hi[4];
    #pragma unroll
    for (int j = 0; j < 4; j++) {
        float2 f = unpack2(cpk[j]);
        lo[j] = f.x; hi[j] = f.y;
    }
    *(float4*)&C[(size_t)(m0 + rb) * ldc + cb] =
        make_float4(lo[0], lo[1], lo[2], lo[3]);
    *(float4*)&C[(size_t)(m0 + rb + 1) * ldc + cb] =
        make_float4(hi[0], hi[1], hi[2], hi[3]);
}

// ---------------------------------------------------------------------------
// RMSNorm over last dim (512). One block per token.
// ---------------------------------------------------------------------------
__global__ void rmsnorm_kernel(const float* __restrict__ h,
                               const float* __restrict__ w,
                               float* __restrict__ out)
{
    const int t = blockIdx.x;
    const float* hp = h + (size_t)t * DMODEL;
    float v0 = hp[threadIdx.x];
    float v1 = hp[threadIdx.x + 256];
    float s = v0 * v0 + v1 * v1;
    #pragma unroll
    for (int o = 16; o; o >>= 1) s += __shfl_xor_sync(0xffffffffu, s, o);

    __shared__ float ws[8];
    __shared__ float rtot;
    if ((threadIdx.x & 31) == 0) ws[threadIdx.x >> 5] = s;
    __syncthreads();
    if (threadIdx.x == 0) {
        float tot = 0.f;
        #pragma unroll
        for (int i = 0; i < 8; i++) tot += ws[i];
        rtot = rsqrtf(tot / (float)DMODEL + 1e-5f);
    }
    __syncthreads();
    const float r = rtot;
    out[(size_t)t * DMODEL + threadIdx.x]       = v0 * r * w[threadIdx.x];
    out[(size_t)t * DMODEL + threadIdx.x + 256] = v1 * r * w[threadIdx.x + 256];
}

// ---------------------------------------------------------------------------
// Depthwise causal conv (k=4) + bias + silu, float4-vectorized (4 ch/thread).
// ---------------------------------------------------------------------------
__device__ __forceinline__ float getc(float4 v, int k) {
    return k == 0 ? v.x : k == 1 ? v.y : k == 2 ? v.z : v.w;
}

__global__ void conv_kernel(const float* __restrict__ xz,
                            const float* __restrict__ cw,
                            const float* __restrict__ cb,
                            float* __restrict__ out)
{
    const int idx = blockIdx.x * blockDim.x + threadIdx.x;   // NTOK*ED/4
    const int e4 = (idx & 255) << 2;
    const int tl = idx >> 8;
    const int t = tl & (SEQL - 1);

    float4 acc = *(const float4*)&cb[e4];
    const float4 w0 = *(const float4*)&cw[(e4 + 0) * DCONV];
    const float4 w1 = *(const float4*)&cw[(e4 + 1) * DCONV];
    const float4 w2 = *(const float4*)&cw[(e4 + 2) * DCONV];
    const float4 w3 = *(const float4*)&cw[(e4 + 3) * DCONV];

    #pragma unroll
    for (int k = 0; k < DCONV; k++) {
        const int tt = t - (DCONV - 1) + k;
        if (tt >= 0) {
            float4 xv = *(const float4*)&xz[(size_t)(tl - (DCONV - 1) + k) * (2 * ED) + e4];
            acc.x = fmaf(getc(w0, k), xv.x, acc.x);
            acc.y = fmaf(getc(w1, k), xv.y, acc.y);
            acc.z = fmaf(getc(w2, k), xv.z, acc.z);
            acc.w = fmaf(getc(w3, k), xv.w, acc.w);
        }
    }
    acc.x = acc.x / (1.f + __expf(-acc.x));
    acc.y = acc.y / (1.f + __expf(-acc.y));
    acc.z = acc.z / (1.f + __expf(-acc.z));
    acc.w = acc.w / (1.f + __expf(-acc.w));
    *(float4*)&out[idx * 4] = acc;
}

// ---------------------------------------------------------------------------
// Selective scan + gating. One warp = 2 channels x 16 states.
// 8-token software pipeline (loads issued one full window ahead).
// Block = 128 threads (4 warps), grid = 256 -> spreads over all SMs.
// ---------------------------------------------------------------------------
__global__ __launch_bounds__(128) void scan_kernel(
    const float* __restrict__ delta,
    const float* __restrict__ xi,
    const float* __restrict__ dbc,
    const float* __restrict__ xz,
    const float* __restrict__ A_log,
    const float* __restrict__ Dp,
    float* __restrict__ y)
{
    const int lane = threadIdx.x & 31;
    const int warp = threadIdx.x >> 5;
    const int n = lane & 15;
    const int g = lane >> 4;
    const int c = blockIdx.x * 8 + warp * 2 + g;
    const int b = c >> 10;
    const int e = c & (ED - 1);

    const float a  = -__expf(A_log[e * DSTATE + n]);
    const float Dv = Dp[e];

    const float* dptr  = delta + (size_t)b * SEQL * ED + e;
    const float* xptr  = xi    + (size_t)b * SEQL * ED + e;
    const float* bcptr = dbc   + (size_t)b * SEQL * 64;
    const float* zptr  = xz    + (size_t)b * SEQL * (2 * ED) + ED + e;
    float*       yptr  = y     + (size_t)b * SEQL * ED + e;

    constexpr int PF = 8;
    float cdv[PF], cxv[PF], cBn[PF], cCn[PF], czv[PF];
    #pragma unroll
    for (int i = 0; i < PF; i++) {
        cdv[i] = __ldg(&dptr[(size_t)i * ED]);
        cxv[i] = __ldg(&xptr[(size_t)i * ED]);
        cBn[i] = __ldg(&bcptr[i * 64 + DTRANK + n]);
        cCn[i] = __ldg(&bcptr[i * 64 + DTRANK + DSTATE + n]);
        czv[i] = __ldg(&zptr[(size_t)i * (2 * ED)]);
    }

    float hs = 0.f;
    for (int t0 = 0; t0 < SEQL; t0 += PF) {
        float ndv[PF], nxv[PF], nBn[PF], nCn[PF], nzv[PF];
        if (t0 + PF < SEQL) {
            #pragma unroll
            for (int i = 0; i < PF; i++) {
                const int t = t0 + PF + i;
                ndv[i] = __ldg(&dptr[(size_t)t * ED]);
                nxv[i] = __ldg(&xptr[(size_t)t * ED]);
                nBn[i] = __ldg(&bcptr[t * 64 + DTRANK + n]);
                nCn[i] = __ldg(&bcptr[t * 64 + DTRANK + DSTATE + n]);
                nzv[i] = __ldg(&zptr[(size_t)t * (2 * ED)]);
            }
        }
        #pragma unroll
        for (int i = 0; i < PF; i++) {
            const float dA = __expf(cdv[i] * a);
            hs = fmaf(dA, hs, cdv[i] * cxv[i] * cBn[i]);
            float p = hs * cCn[i];
            p += __shfl_xor_sync(0xffffffffu, p, 8);
            p += __shfl_xor_sync(0xffffffffu, p, 4);
            p += __shfl_xor_sync(0xffffffffu, p, 2);
            p += __shfl_xor_sync(0xffffffffu, p, 1);
            if (n == 0) {
                const float zv = czv[i];
                const float silu_z = zv / (1.f + __expf(-zv));
                yptr[(size_t)(t0 + i) * ED] = (p + Dv * cxv[i]) * silu_z;
            }
        }
        #pragma unroll
        for (int i = 0; i < PF; i++) {
            cdv[i] = ndv[i]; cxv[i] = nxv[i]; cBn[i] = nBn[i];
            cCn[i] = nCn[i]; czv[i] = nzv[i];
        }
    }
}

// ---------------------------------------------------------------------------
// Host launch
// ---------------------------------------------------------------------------
extern "C" void kernel_launch(void* const* d_in, const int* in_sizes, int n_in,
                              void* d_out, int out_size)
{
    const float* x        = (const float*)d_in[0];
    const float* emb_w    = (const float*)d_in[1];
    const float* emb_b    = (const float*)d_in[2];
    const float* in_w     = (const float*)d_in[3];
    const float* conv_w   = (const float*)d_in[4];
    const float* conv_b   = (const float*)d_in[5];
    const float* xp_w     = (const float*)d_in[6];
    const float* dt_w     = (const float*)d_in[7];
    const float* dt_b     = (const float*)d_in[8];
    const float* A_log    = (const float*)d_in[9];
    const float* Dparam   = (const float*)d_in[10];
    const float* out_w    = (const float*)d_in[11];
    const float* norm_w   = (const float*)d_in[12];
    float* h = (float*)d_out;

    float *hn, *xz, *xic, *dbc, *delta, *yb;
    cudaGetSymbolAddress((void**)&hn,    g_hn);
    cudaGetSymbolAddress((void**)&xz,    g_xz);
    cudaGetSymbolAddress((void**)&xic,   g_xic);
    cudaGetSymbolAddress((void**)&dbc,   g_dbc);
    cudaGetSymbolAddress((void**)&delta, g_delta);
    cudaGetSymbolAddress((void**)&yb,    g_y);

    // Embedding: h = x @ emb_w^T + emb_b  (M=4096, N=512, K=64)
    fgemm<64, true, false, false><<<dim3(DMODEL / 64, NTOK / 128), 256>>>(
        x, 64, emb_w, 64, emb_b, h, DMODEL, 64);

    for (int layer = 0; layer < NLAYERS; layer++) {
        const float* l_in_w   = in_w   + (size_t)layer * 2 * ED * DMODEL;
        const float* l_conv_w = conv_w + (size_t)layer * ED * DCONV;
        const float* l_conv_b = conv_b + (size_t)layer * ED;
        const float* l_xp_w   = xp_w   + (size_t)layer * 64 * ED;
        const float* l_dt_w   = dt_w   + (size_t)layer * ED * DTRANK;
        const float* l_dt_b   = dt_b   + (size_t)layer * ED;
        const float* l_A_log  = A_log  + (size_t)layer * ED * DSTATE;
        const float* l_D      = Dparam + (size_t)layer * ED;
        const float* l_out_w  = out_w  + (size_t)layer * DMODEL * ED;
        const float* l_norm_w = norm_w + (size_t)layer * DMODEL;

        // 1. hn = rmsnorm(h)
        rmsnorm_kernel<<<NTOK, 256>>>(h, l_norm_w, hn);

        // 2. xz = hn @ in_proj^T  (M=4096, N=2048, K=512)
        fgemm<128, false, false, false><<<dim3(2 * ED / 128, NTOK / 128), 256>>>(
            hn, DMODEL, l_in_w, DMODEL, nullptr, xz, 2 * ED, DMODEL);

        // 3. xi = silu(conv(xz[:, :ED]) + cb)
        conv_kernel<<<(NTOK * ED / 4) / 256, 256>>>(xz, l_conv_w, l_conv_b, xic);

        // 4. dbc = xi @ x_proj^T  (M=4096, N=64, K=1024) — BM=32 grid fill
        fgemm32<<<dim3(1, NTOK / 32), 256>>>(xic, ED, l_xp_w, ED, dbc, 64, ED);

        // 5. delta = softplus(dbc[:, :32] @ dt_proj^T + dt_b)  (M=4096, N=1024, K=32)
        fgemm<128, true, false, true><<<dim3(ED / 128, NTOK / 128), 256>>>(
            dbc, 64, l_dt_w, DTRANK, l_dt_b, delta, ED, DTRANK);

        // 6. scan + gating -> y
        scan_kernel<<<(BATCH * ED) / 8, 128>>>(delta, xic, dbc, xz,
                                               l_A_log, l_D, yb);

        // 7. h += y @ out_proj^T  (M=4096, N=512, K=1024)
        fgemm<64, false, true, false><<<dim3(DMODEL / 64, NTOK / 128), 256>>>(
            yb, ED, l_out_w, ED, nullptr, h, DMODEL, ED);
    }
}

// round 6
// speedup vs baseline: 2.5817x; 1.0570x over previous
#include <cuda_runtime.h>
#include <math.h>
#include <cstdint>

// Problem constants
#define BATCH 2
#define SEQL 2048
#define NTOK (BATCH * SEQL)          // 4096
#define DMODEL 512
#define ED 1024
#define DSTATE 16
#define DCONV 4
#define DTRANK 32
#define NLAYERS 2

// Scratch buffers (no cudaMalloc allowed)
__device__ float g_xz[NTOK * 2 * ED];
__device__ float g_xic[NTOK * ED];
__device__ float g_dbc[NTOK * 64];
__device__ float g_delta[NTOK * ED];
__device__ float g_y[NTOK * ED];

__device__ __forceinline__ float softplus_f(float v) {
    return (v > 20.f) ? v : log1pf(__expf(v));
}

// ---------------------------------------------------------------------------
// Packed fp32 helpers (Blackwell f32x2)
// ---------------------------------------------------------------------------
typedef unsigned long long u64t;

__device__ __forceinline__ u64t dup2f(float v) {
    u64t r; unsigned u = __float_as_uint(v);
    asm("mov.b64 %0, {%1, %1};" : "=l"(r) : "r"(u));
    return r;
}
__device__ __forceinline__ void ffma2(u64t& c, u64t a, u64t b) {
    asm("fma.rn.f32x2 %0, %1, %2, %0;" : "+l"(c) : "l"(a), "l"(b));
}
__device__ __forceinline__ float2 unpack2(u64t p) {
    unsigned lo, hi;
    asm("mov.b64 {%0, %1}, %2;" : "=r"(lo), "=r"(hi) : "l"(p));
    return make_float2(__uint_as_float(lo), __uint_as_float(hi));
}

// ---------------------------------------------------------------------------
// fp32 FFMA2 GEMM:  C[M,N] (=, +=) A[M,K] @ W[N,K]^T
// Options: +bias, +softplus, NORMW (fold nw[k] into B while staging),
// ROWSCALE (rmsnorm row scale r_t computed in-kernel from A, applied in
// epilogue — requires lda == K).
// BM=128, BN=TILE_N (128/64), BK=16, 256 threads, smem k-major double buffer.
// ---------------------------------------------------------------------------
template <int TILE_N, bool BIAS, bool ACCUM, bool SOFTPLUS, bool NORMW, bool ROWSCALE>
__global__ __launch_bounds__(256) void fgemm(
    const float* __restrict__ A, int lda,
    const float* __restrict__ W, int ldw,
    const float* __restrict__ bias,
    const float* __restrict__ nw,
    float* __restrict__ C, int ldc, int K)
{
    constexpr int BK = 16, STA = 132, STB = TILE_N + 4;
    constexpr int NBCH = TILE_N / 64;        // B chunks per thread (1 or 2)
    constexpr int TC = TILE_N / 16;          // thread tile cols: 8 or 4

    __shared__ float sA[2][BK * STA];
    __shared__ float sB[2][BK * STB];
    __shared__ float rbuf[128];

    const int tid = threadIdx.x;
    const int wid = tid >> 5, lane = tid & 31;
    const int ly = lane >> 3, lx = lane & 7;
    const int wy = wid >> 1, wx = wid & 1;
    const int rb = wy * 32 + ly * 8;
    const int cb = wx * (TILE_N / 2) + lx * TC;
    const int m0 = blockIdx.y * 128;
    const int n0 = blockIdx.x * TILE_N;

    // tile-load indexing: chunk = (row, quad); thread covers rows r and r+64
    const int arow = tid >> 2, aq = tid & 3;

    u64t cpk[4][TC] = {};
    float sq0 = 0.f, sq1 = 0.f;
    const int KT = K / BK;

    float4 va0, va1, vb0, vb1, vnw;
    va0 = *(const float4*)&A[(size_t)(m0 + arow) * lda + aq * 4];
    va1 = *(const float4*)&A[(size_t)(m0 + arow + 64) * lda + aq * 4];
    vb0 = *(const float4*)&W[(size_t)(n0 + arow) * ldw + aq * 4];
    if (NBCH == 2) vb1 = *(const float4*)&W[(size_t)(n0 + arow + 64) * ldw + aq * 4];
    if (NORMW) vnw = *(const float4*)&nw[aq * 4];

    for (int kt = 0; kt < KT; kt++) {
        const int buf = kt & 1;
        {
            float* d0 = &sA[buf][(aq * 4) * STA + arow];
            d0[0] = va0.x; d0[STA] = va0.y; d0[2 * STA] = va0.z; d0[3 * STA] = va0.w;
            float* d1 = d0 + 64;
            d1[0] = va1.x; d1[STA] = va1.y; d1[2 * STA] = va1.z; d1[3 * STA] = va1.w;
        }
        if (ROWSCALE) {
            sq0 = fmaf(va0.x, va0.x, fmaf(va0.y, va0.y,
                  fmaf(va0.z, va0.z, fmaf(va0.w, va0.w, sq0))));
            sq1 = fmaf(va1.x, va1.x, fmaf(va1.y, va1.y,
                  fmaf(va1.z, va1.z, fmaf(va1.w, va1.w, sq1))));
        }
        {
            float4 b0 = vb0, b1 = vb1;
            if (NORMW) {
                b0.x *= vnw.x; b0.y *= vnw.y; b0.z *= vnw.z; b0.w *= vnw.w;
                if (NBCH == 2) {
                    b1.x *= vnw.x; b1.y *= vnw.y; b1.z *= vnw.z; b1.w *= vnw.w;
                }
            }
            float* d0 = &sB[buf][(aq * 4) * STB + arow];
            d0[0] = b0.x; d0[STB] = b0.y; d0[2 * STB] = b0.z; d0[3 * STB] = b0.w;
            if (NBCH == 2) {
                float* d1 = d0 + 64;
                d1[0] = b1.x; d1[STB] = b1.y; d1[2 * STB] = b1.z; d1[3 * STB] = b1.w;
            }
        }
        __syncthreads();

        if (kt + 1 < KT) {
            const int k0 = (kt + 1) * BK;
            va0 = *(const float4*)&A[(size_t)(m0 + arow) * lda + k0 + aq * 4];
            va1 = *(const float4*)&A[(size_t)(m0 + arow + 64) * lda + k0 + aq * 4];
            vb0 = *(const float4*)&W[(size_t)(n0 + arow) * ldw + k0 + aq * 4];
            if (NBCH == 2)
                vb1 = *(const float4*)&W[(size_t)(n0 + arow + 64) * ldw + k0 + aq * 4];
            if (NORMW) vnw = *(const float4*)&nw[k0 + aq * 4];
        }

        const float* bufA = sA[buf];
        const float* bufB = sB[buf];
        #pragma unroll
        for (int k = 0; k < BK; k++) {
            const ulonglong2 a0 = *(const ulonglong2*)&bufA[k * STA + rb];
            const ulonglong2 a1 = *(const ulonglong2*)&bufA[k * STA + rb + 4];
            const u64t ap[4] = {a0.x, a0.y, a1.x, a1.y};
            float4 b0 = *(const float4*)&bufB[k * STB + cb];
            float4 b1;
            if (TC == 8) b1 = *(const float4*)&bufB[k * STB + cb + 4];
            u64t bd[TC];
            bd[0] = dup2f(b0.x); bd[1] = dup2f(b0.y);
            bd[2] = dup2f(b0.z); bd[3] = dup2f(b0.w);
            if (TC == 8) {
                bd[4] = dup2f(b1.x); bd[5] = dup2f(b1.y);
                bd[6] = dup2f(b1.z); bd[7] = dup2f(b1.w);
            }
            #pragma unroll
            for (int ih = 0; ih < 4; ih++)
                #pragma unroll
                for (int j = 0; j < TC; j++)
                    ffma2(cpk[ih][j], ap[ih], bd[j]);
        }
        __syncthreads();
    }

    if (ROWSCALE) {
        float s0 = sq0 + __shfl_xor_sync(0xffffffffu, sq0, 1);
        s0 += __shfl_xor_sync(0xffffffffu, s0, 2);
        float s1 = sq1 + __shfl_xor_sync(0xffffffffu, sq1, 1);
        s1 += __shfl_xor_sync(0xffffffffu, s1, 2);
        if ((lane & 3) == 0) {
            rbuf[arow]      = rsqrtf(s0 / (float)K + 1e-5f);
            rbuf[arow + 64] = rsqrtf(s1 / (float)K + 1e-5f);
        }
        __syncthreads();
    }

    // epilogue
    float bias_r[TC];
    if (BIAS) {
        #pragma unroll
        for (int j = 0; j < TC; j++) bias_r[j] = bias[n0 + cb + j];
    }
    #pragma unroll
    for (int ih = 0; ih < 4; ih++) {
        float lo[TC], hi[TC];
        #pragma unroll
        for (int j = 0; j < TC; j++) {
            float2 f = unpack2(cpk[ih][j]);
            lo[j] = f.x; hi[j] = f.y;
        }
        #pragma unroll
        for (int half = 0; half < 2; half++) {
            const float* src = half ? hi : lo;
            const int rt = rb + 2 * ih + half;
            const int row = m0 + rt;
            const float scale = ROWSCALE ? rbuf[rt] : 1.f;
            float* cp = &C[(size_t)row * ldc + n0 + cb];
            #pragma unroll
            for (int j4 = 0; j4 < TC / 4; j4++) {
                float4 v = make_float4(src[j4 * 4 + 0], src[j4 * 4 + 1],
                                       src[j4 * 4 + 2], src[j4 * 4 + 3]);
                if (ROWSCALE) { v.x *= scale; v.y *= scale; v.z *= scale; v.w *= scale; }
                if (BIAS) {
                    v.x += bias_r[j4 * 4 + 0]; v.y += bias_r[j4 * 4 + 1];
                    v.z += bias_r[j4 * 4 + 2]; v.w += bias_r[j4 * 4 + 3];
                }
                if (SOFTPLUS) {
                    v.x = softplus_f(v.x); v.y = softplus_f(v.y);
                    v.z = softplus_f(v.z); v.w = softplus_f(v.w);
                }
                if (ACCUM) {
                    float4 o = *(const float4*)&cp[j4 * 4];
                    v.x += o.x; v.y += o.y; v.z += o.z; v.w += o.w;
                }
                *(float4*)&cp[j4 * 4] = v;
            }
        }
    }
}

// ---------------------------------------------------------------------------
// Small-M GEMM for x_proj (M=4096, N=64, K=1024): BM=32, BN=64, BK=16,
// 256 threads -> grid (1, 128). Thread tile 2x4 (one m-pair).
// ---------------------------------------------------------------------------
__global__ __launch_bounds__(256) void fgemm32(
    const float* __restrict__ A, int lda,
    const float* __restrict__ W, int ldw,
    float* __restrict__ C, int ldc, int K)
{
    constexpr int BK = 16, STA = 36, STB = 68;

    __shared__ float sA[2][BK * STA];
    __shared__ float sB[2][BK * STB];

    const int tid = threadIdx.x;
    const int wid = tid >> 5, lane = tid & 31;
    const int ly = lane >> 3, lx = lane & 7;
    const int wy = wid >> 1, wx = wid & 1;
    const int rb = wy * 8 + ly * 2;
    const int cb = wx * 32 + lx * 4;
    const int m0 = blockIdx.y * 32;

    const int arow = tid >> 2, aq = tid & 3;   // A: tid<128; B: all threads
    const bool aact = tid < 128;

    u64t cpk[4] = {};
    const int KT = K / BK;

    float4 va, vb;
    if (aact) va = *(const float4*)&A[(size_t)(m0 + arow) * lda + aq * 4];
    vb = *(const float4*)&W[(size_t)arow * ldw + aq * 4];

    for (int kt = 0; kt < KT; kt++) {
        const int buf = kt & 1;
        if (aact) {
            float* d = &sA[buf][(aq * 4) * STA + arow];
            d[0] = va.x; d[STA] = va.y; d[2 * STA] = va.z; d[3 * STA] = va.w;
        }
        {
            float* d = &sB[buf][(aq * 4) * STB + arow];
            d[0] = vb.x; d[STB] = vb.y; d[2 * STB] = vb.z; d[3 * STB] = vb.w;
        }
        __syncthreads();

        if (kt + 1 < KT) {
            const int k0 = (kt + 1) * BK;
            if (aact) va = *(const float4*)&A[(size_t)(m0 + arow) * lda + k0 + aq * 4];
            vb = *(const float4*)&W[(size_t)arow * ldw + k0 + aq * 4];
        }

        const float* bufA = sA[buf];
        const float* bufB = sB[buf];
        #pragma unroll
        for (int k = 0; k < BK; k++) {
            const u64t ap = *(const u64t*)&bufA[k * STA + rb];
            float4 b0 = *(const float4*)&bufB[k * STB + cb];
            ffma2(cpk[0], ap, dup2f(b0.x));
            ffma2(cpk[1], ap, dup2f(b0.y));
            ffma2(cpk[2], ap, dup2f(b0.z));
            ffma2(cpk[3], ap, dup2f(b0.w));
        }
        __syncthreads();
    }

    float lo[4], hi[4];
    #pragma unroll
    for (int j = 0; j < 4; j++) {
        float2 f = unpack2(cpk[j]);
        lo[j] = f.x; hi[j] = f.y;
    }
    *(float4*)&C[(size_t)(m0 + rb) * ldc + cb] =
        make_float4(lo[0], lo[1], lo[2], lo[3]);
    *(float4*)&C[(size_t)(m0 + rb + 1) * ldc + cb] =
        make_float4(hi[0], hi[1], hi[2], hi[3]);
}

// ---------------------------------------------------------------------------
// Depthwise causal conv (k=4) + bias + silu, float4-vectorized.
// ---------------------------------------------------------------------------
__device__ __forceinline__ float getc(float4 v, int k) {
    return k == 0 ? v.x : k == 1 ? v.y : k == 2 ? v.z : v.w;
}

__global__ void conv_kernel(const float* __restrict__ xz,
                            const float* __restrict__ cw,
                            const float* __restrict__ cb,
                            float* __restrict__ out)
{
    const int idx = blockIdx.x * blockDim.x + threadIdx.x;   // NTOK*ED/4
    const int e4 = (idx & 255) << 2;
    const int tl = idx >> 8;
    const int t = tl & (SEQL - 1);

    float4 acc = *(const float4*)&cb[e4];
    const float4 w0 = *(const float4*)&cw[(e4 + 0) * DCONV];
    const float4 w1 = *(const float4*)&cw[(e4 + 1) * DCONV];
    const float4 w2 = *(const float4*)&cw[(e4 + 2) * DCONV];
    const float4 w3 = *(const float4*)&cw[(e4 + 3) * DCONV];

    #pragma unroll
    for (int k = 0; k < DCONV; k++) {
        const int tt = t - (DCONV - 1) + k;
        if (tt >= 0) {
            float4 xv = *(const float4*)&xz[(size_t)(tl - (DCONV - 1) + k) * (2 * ED) + e4];
            acc.x = fmaf(getc(w0, k), xv.x, acc.x);
            acc.y = fmaf(getc(w1, k), xv.y, acc.y);
            acc.z = fmaf(getc(w2, k), xv.z, acc.z);
            acc.w = fmaf(getc(w3, k), xv.w, acc.w);
        }
    }
    acc.x = acc.x / (1.f + __expf(-acc.x));
    acc.y = acc.y / (1.f + __expf(-acc.y));
    acc.z = acc.z / (1.f + __expf(-acc.z));
    acc.w = acc.w / (1.f + __expf(-acc.w));
    *(float4*)&out[idx * 4] = acc;
}

// ---------------------------------------------------------------------------
// Selective scan + gating. One warp = 2 channels x 16 states; 8-token pipeline.
// ---------------------------------------------------------------------------
__global__ __launch_bounds__(128) void scan_kernel(
    const float* __restrict__ delta,
    const float* __restrict__ xi,
    const float* __restrict__ dbc,
    const float* __restrict__ xz,
    const float* __restrict__ A_log,
    const float* __restrict__ Dp,
    float* __restrict__ y)
{
    const int lane = threadIdx.x & 31;
    const int warp = threadIdx.x >> 5;
    const int n = lane & 15;
    const int g = lane >> 4;
    const int c = blockIdx.x * 8 + warp * 2 + g;
    const int b = c >> 10;
    const int e = c & (ED - 1);

    const float a  = -__expf(A_log[e * DSTATE + n]);
    const float Dv = Dp[e];

    const float* dptr  = delta + (size_t)b * SEQL * ED + e;
    const float* xptr  = xi    + (size_t)b * SEQL * ED + e;
    const float* bcptr = dbc   + (size_t)b * SEQL * 64;
    const float* zptr  = xz    + (size_t)b * SEQL * (2 * ED) + ED + e;
    float*       yptr  = y     + (size_t)b * SEQL * ED + e;

    constexpr int PF = 8;
    float cdv[PF], cxv[PF], cBn[PF], cCn[PF], czv[PF];
    #pragma unroll
    for (int i = 0; i < PF; i++) {
        cdv[i] = __ldg(&dptr[(size_t)i * ED]);
        cxv[i] = __ldg(&xptr[(size_t)i * ED]);
        cBn[i] = __ldg(&bcptr[i * 64 + DTRANK + n]);
        cCn[i] = __ldg(&bcptr[i * 64 + DTRANK + DSTATE + n]);
        czv[i] = __ldg(&zptr[(size_t)i * (2 * ED)]);
    }

    float hs = 0.f;
    for (int t0 = 0; t0 < SEQL; t0 += PF) {
        float ndv[PF], nxv[PF], nBn[PF], nCn[PF], nzv[PF];
        if (t0 + PF < SEQL) {
            #pragma unroll
            for (int i = 0; i < PF; i++) {
                const int t = t0 + PF + i;
                ndv[i] = __ldg(&dptr[(size_t)t * ED]);
                nxv[i] = __ldg(&xptr[(size_t)t * ED]);
                nBn[i] = __ldg(&bcptr[t * 64 + DTRANK + n]);
                nCn[i] = __ldg(&bcptr[t * 64 + DTRANK + DSTATE + n]);
                nzv[i] = __ldg(&zptr[(size_t)t * (2 * ED)]);
            }
        }
        #pragma unroll
        for (int i = 0; i < PF; i++) {
            const float dA = __expf(cdv[i] * a);
            hs = fmaf(dA, hs, cdv[i] * cxv[i] * cBn[i]);
            float p = hs * cCn[i];
            p += __shfl_xor_sync(0xffffffffu, p, 8);
            p += __shfl_xor_sync(0xffffffffu, p, 4);
            p += __shfl_xor_sync(0xffffffffu, p, 2);
            p += __shfl_xor_sync(0xffffffffu, p, 1);
            if (n == 0) {
                const float zv = czv[i];
                const float silu_z = zv / (1.f + __expf(-zv));
                yptr[(size_t)(t0 + i) * ED] = (p + Dv * cxv[i]) * silu_z;
            }
        }
        #pragma unroll
        for (int i = 0; i < PF; i++) {
            cdv[i] = ndv[i]; cxv[i] = nxv[i]; cBn[i] = nBn[i];
            cCn[i] = nCn[i]; czv[i] = nzv[i];
        }
    }
}

// ---------------------------------------------------------------------------
// Host launch
// ---------------------------------------------------------------------------
extern "C" void kernel_launch(void* const* d_in, const int* in_sizes, int n_in,
                              void* d_out, int out_size)
{
    const float* x        = (const float*)d_in[0];
    const float* emb_w    = (const float*)d_in[1];
    const float* emb_b    = (const float*)d_in[2];
    const float* in_w     = (const float*)d_in[3];
    const float* conv_w   = (const float*)d_in[4];
    const float* conv_b   = (const float*)d_in[5];
    const float* xp_w     = (const float*)d_in[6];
    const float* dt_w     = (const float*)d_in[7];
    const float* dt_b     = (const float*)d_in[8];
    const float* A_log    = (const float*)d_in[9];
    const float* Dparam   = (const float*)d_in[10];
    const float* out_w    = (const float*)d_in[11];
    const float* norm_w   = (const float*)d_in[12];
    float* h = (float*)d_out;

    float *xz, *xic, *dbc, *delta, *yb;
    cudaGetSymbolAddress((void**)&xz,    g_xz);
    cudaGetSymbolAddress((void**)&xic,   g_xic);
    cudaGetSymbolAddress((void**)&dbc,   g_dbc);
    cudaGetSymbolAddress((void**)&delta, g_delta);
    cudaGetSymbolAddress((void**)&yb,    g_y);

    // Embedding: h = x @ emb_w^T + emb_b  (M=4096, N=512, K=64)
    fgemm<64, true, false, false, false, false>
        <<<dim3(DMODEL / 64, NTOK / 128), 256>>>(
        x, 64, emb_w, 64, emb_b, nullptr, h, DMODEL, 64);

    for (int layer = 0; layer < NLAYERS; layer++) {
        const float* l_in_w   = in_w   + (size_t)layer * 2 * ED * DMODEL;
        const float* l_conv_w = conv_w + (size_t)layer * ED * DCONV;
        const float* l_conv_b = conv_b + (size_t)layer * ED;
        const float* l_xp_w   = xp_w   + (size_t)layer * 64 * ED;
        const float* l_dt_w   = dt_w   + (size_t)layer * ED * DTRANK;
        const float* l_dt_b   = dt_b   + (size_t)layer * ED;
        const float* l_A_log  = A_log  + (size_t)layer * ED * DSTATE;
        const float* l_D      = Dparam + (size_t)layer * ED;
        const float* l_out_w  = out_w  + (size_t)layer * DMODEL * ED;
        const float* l_norm_w = norm_w + (size_t)layer * DMODEL;

        // 1+2. xz = rmsnorm(h) @ in_proj^T, norm fused (M=4096, N=2048, K=512)
        fgemm<128, false, false, false, true, true>
            <<<dim3(2 * ED / 128, NTOK / 128), 256>>>(
            h, DMODEL, l_in_w, DMODEL, nullptr, l_norm_w, xz, 2 * ED, DMODEL);

        // 3. xi = silu(conv(xz[:, :ED]) + cb)
        conv_kernel<<<(NTOK * ED / 4) / 256, 256>>>(xz, l_conv_w, l_conv_b, xic);

        // 4. dbc = xi @ x_proj^T  (M=4096, N=64, K=1024)
        fgemm32<<<dim3(1, NTOK / 32), 256>>>(xic, ED, l_xp_w, ED, dbc, 64, ED);

        // 5. delta = softplus(dbc[:, :32] @ dt_proj^T + dt_b)  (M=4096, N=1024, K=32)
        fgemm<128, true, false, true, false, false>
            <<<dim3(ED / 128, NTOK / 128), 256>>>(
            dbc, 64, l_dt_w, DTRANK, l_dt_b, nullptr, delta, ED, DTRANK);

        // 6. scan + gating -> y
        scan_kernel<<<(BATCH * ED) / 8, 128>>>(delta, xic, dbc, xz,
                                               l_A_log, l_D, yb);

        // 7. h += y @ out_proj^T  (M=4096, N=512, K=1024)
        fgemm<64, false, true, false, false, false>
            <<<dim3(DMODEL / 64, NTOK / 128), 256>>>(
            yb, ED, l_out_w, ED, nullptr, nullptr, h, DMODEL, ED);
    }
}

// round 7
// speedup vs baseline: 3.2601x; 1.2628x over previous
#include <cuda_runtime.h>
#include <math.h>
#include <cstdint>

// Problem constants
#define BATCH 2
#define SEQL 2048
#define NTOK (BATCH * SEQL)          // 4096
#define DMODEL 512
#define ED 1024
#define DSTATE 16
#define DCONV 4
#define DTRANK 32
#define NLAYERS 2

// Scratch buffers (no cudaMalloc allowed)
__device__ float g_xz[NTOK * 2 * ED];
__device__ float g_xic[NTOK * ED];
__device__ float g_dbc[NTOK * 64];
__device__ float g_dbcp[4 * NTOK * 64];   // split-K partials for x_proj
__device__ float g_delta[NTOK * ED];
__device__ float g_y[NTOK * ED];

__device__ __forceinline__ float softplus_f(float v) {
    return (v > 20.f) ? v : log1pf(__expf(v));
}

// ---------------------------------------------------------------------------
// Packed fp32 helpers (Blackwell f32x2)
// ---------------------------------------------------------------------------
typedef unsigned long long u64t;

__device__ __forceinline__ u64t dup2f(float v) {
    u64t r; unsigned u = __float_as_uint(v);
    asm("mov.b64 %0, {%1, %1};" : "=l"(r) : "r"(u));
    return r;
}
__device__ __forceinline__ void ffma2(u64t& c, u64t a, u64t b) {
    asm("fma.rn.f32x2 %0, %1, %2, %0;" : "+l"(c) : "l"(a), "l"(b));
}
__device__ __forceinline__ float2 unpack2(u64t p) {
    unsigned lo, hi;
    asm("mov.b64 {%0, %1}, %2;" : "=r"(lo), "=r"(hi) : "l"(p));
    return make_float2(__uint_as_float(lo), __uint_as_float(hi));
}

// ---------------------------------------------------------------------------
// fp32 FFMA2 GEMM:  C[M,N] (=, +=) A[M,K] @ W[N,K]^T
// Options: +bias, +softplus, NORMW (fold nw[k] into B), ROWSCALE (rmsnorm
// row scale from A, needs lda==K), SPLITK (blockIdx.z k-slice, partial out).
// BM=128, BN=TILE_N (128/64), BK=16, 256 threads, smem k-major double buffer.
// ---------------------------------------------------------------------------
template <int TILE_N, bool BIAS, bool ACCUM, bool SOFTPLUS, bool NORMW,
          bool ROWSCALE, int SPLITK = 1>
__global__ __launch_bounds__(256) void fgemm(
    const float* __restrict__ A, int lda,
    const float* __restrict__ W, int ldw,
    const float* __restrict__ bias,
    const float* __restrict__ nw,
    float* __restrict__ C, int ldc, int K)
{
    constexpr int BK = 16, STA = 132, STB = TILE_N + 4;
    constexpr int NBCH = TILE_N / 64;
    constexpr int TC = TILE_N / 16;

    __shared__ float sA[2][BK * STA];
    __shared__ float sB[2][BK * STB];
    __shared__ float rbuf[128];

    const int tid = threadIdx.x;
    const int wid = tid >> 5, lane = tid & 31;
    const int ly = lane >> 3, lx = lane & 7;
    const int wy = wid >> 1, wx = wid & 1;
    const int rb = wy * 32 + ly * 8;
    const int cb = wx * (TILE_N / 2) + lx * TC;
    const int m0 = blockIdx.y * 128;
    const int n0 = blockIdx.x * TILE_N;

    if (SPLITK > 1) {
        const int ks = blockIdx.z * (K / SPLITK);
        A += ks; W += ks;
        C += (size_t)blockIdx.z * gridDim.y * 128 * ldc;
        K = K / SPLITK;
    }

    const int arow = tid >> 2, aq = tid & 3;

    u64t cpk[4][TC] = {};
    float sq0 = 0.f, sq1 = 0.f;
    const int KT = K / BK;

    float4 va0, va1, vb0, vnw;
    float4 vb1 = make_float4(0.f, 0.f, 0.f, 0.f);
    va0 = *(const float4*)&A[(size_t)(m0 + arow) * lda + aq * 4];
    va1 = *(const float4*)&A[(size_t)(m0 + arow + 64) * lda + aq * 4];
    vb0 = *(const float4*)&W[(size_t)(n0 + arow) * ldw + aq * 4];
    if (NBCH == 2) vb1 = *(const float4*)&W[(size_t)(n0 + arow + 64) * ldw + aq * 4];
    if (NORMW) vnw = *(const float4*)&nw[aq * 4];

    for (int kt = 0; kt < KT; kt++) {
        const int buf = kt & 1;
        {
            float* d0 = &sA[buf][(aq * 4) * STA + arow];
            d0[0] = va0.x; d0[STA] = va0.y; d0[2 * STA] = va0.z; d0[3 * STA] = va0.w;
            float* d1 = d0 + 64;
            d1[0] = va1.x; d1[STA] = va1.y; d1[2 * STA] = va1.z; d1[3 * STA] = va1.w;
        }
        if (ROWSCALE) {
            sq0 = fmaf(va0.x, va0.x, fmaf(va0.y, va0.y,
                  fmaf(va0.z, va0.z, fmaf(va0.w, va0.w, sq0))));
            sq1 = fmaf(va1.x, va1.x, fmaf(va1.y, va1.y,
                  fmaf(va1.z, va1.z, fmaf(va1.w, va1.w, sq1))));
        }
        {
            float4 b0 = vb0, b1 = vb1;
            if (NORMW) {
                b0.x *= vnw.x; b0.y *= vnw.y; b0.z *= vnw.z; b0.w *= vnw.w;
                if (NBCH == 2) {
                    b1.x *= vnw.x; b1.y *= vnw.y; b1.z *= vnw.z; b1.w *= vnw.w;
                }
            }
            float* d0 = &sB[buf][(aq * 4) * STB + arow];
            d0[0] = b0.x; d0[STB] = b0.y; d0[2 * STB] = b0.z; d0[3 * STB] = b0.w;
            if (NBCH == 2) {
                float* d1 = d0 + 64;
                d1[0] = b1.x; d1[STB] = b1.y; d1[2 * STB] = b1.z; d1[3 * STB] = b1.w;
            }
        }
        __syncthreads();

        if (kt + 1 < KT) {
            const int k0 = (kt + 1) * BK;
            va0 = *(const float4*)&A[(size_t)(m0 + arow) * lda + k0 + aq * 4];
            va1 = *(const float4*)&A[(size_t)(m0 + arow + 64) * lda + k0 + aq * 4];
            vb0 = *(const float4*)&W[(size_t)(n0 + arow) * ldw + k0 + aq * 4];
            if (NBCH == 2)
                vb1 = *(const float4*)&W[(size_t)(n0 + arow + 64) * ldw + k0 + aq * 4];
            if (NORMW) vnw = *(const float4*)&nw[k0 + aq * 4];
        }

        const float* bufA = sA[buf];
        const float* bufB = sB[buf];
        #pragma unroll
        for (int k = 0; k < BK; k++) {
            const ulonglong2 a0 = *(const ulonglong2*)&bufA[k * STA + rb];
            const ulonglong2 a1 = *(const ulonglong2*)&bufA[k * STA + rb + 4];
            const u64t ap[4] = {a0.x, a0.y, a1.x, a1.y};
            float4 b0 = *(const float4*)&bufB[k * STB + cb];
            float4 b1;
            if (TC == 8) b1 = *(const float4*)&bufB[k * STB + cb + 4];
            u64t bd[TC];
            bd[0] = dup2f(b0.x); bd[1] = dup2f(b0.y);
            bd[2] = dup2f(b0.z); bd[3] = dup2f(b0.w);
            if (TC == 8) {
                bd[4] = dup2f(b1.x); bd[5] = dup2f(b1.y);
                bd[6] = dup2f(b1.z); bd[7] = dup2f(b1.w);
            }
            #pragma unroll
            for (int ih = 0; ih < 4; ih++)
                #pragma unroll
                for (int j = 0; j < TC; j++)
                    ffma2(cpk[ih][j], ap[ih], bd[j]);
        }
        __syncthreads();
    }

    if (ROWSCALE) {
        float s0 = sq0 + __shfl_xor_sync(0xffffffffu, sq0, 1);
        s0 += __shfl_xor_sync(0xffffffffu, s0, 2);
        float s1 = sq1 + __shfl_xor_sync(0xffffffffu, sq1, 1);
        s1 += __shfl_xor_sync(0xffffffffu, s1, 2);
        if ((lane & 3) == 0) {
            rbuf[arow]      = rsqrtf(s0 / (float)K + 1e-5f);
            rbuf[arow + 64] = rsqrtf(s1 / (float)K + 1e-5f);
        }
        __syncthreads();
    }

    float bias_r[TC];
    if (BIAS) {
        #pragma unroll
        for (int j = 0; j < TC; j++) bias_r[j] = bias[n0 + cb + j];
    }
    #pragma unroll
    for (int ih = 0; ih < 4; ih++) {
        float lo[TC], hi[TC];
        #pragma unroll
        for (int j = 0; j < TC; j++) {
            float2 f = unpack2(cpk[ih][j]);
            lo[j] = f.x; hi[j] = f.y;
        }
        #pragma unroll
        for (int half = 0; half < 2; half++) {
            const float* src = half ? hi : lo;
            const int rt = rb + 2 * ih + half;
            const int row = m0 + rt;
            const float scale = ROWSCALE ? rbuf[rt] : 1.f;
            float* cp = &C[(size_t)row * ldc + n0 + cb];
            #pragma unroll
            for (int j4 = 0; j4 < TC / 4; j4++) {
                float4 v = make_float4(src[j4 * 4 + 0], src[j4 * 4 + 1],
                                       src[j4 * 4 + 2], src[j4 * 4 + 3]);
                if (ROWSCALE) { v.x *= scale; v.y *= scale; v.z *= scale; v.w *= scale; }
                if (BIAS) {
                    v.x += bias_r[j4 * 4 + 0]; v.y += bias_r[j4 * 4 + 1];
                    v.z += bias_r[j4 * 4 + 2]; v.w += bias_r[j4 * 4 + 3];
                }
                if (SOFTPLUS) {
                    v.x = softplus_f(v.x); v.y = softplus_f(v.y);
                    v.z = softplus_f(v.z); v.w = softplus_f(v.w);
                }
                if (ACCUM) {
                    float4 o = *(const float4*)&cp[j4 * 4];
                    v.x += o.x; v.y += o.y; v.z += o.z; v.w += o.w;
                }
                *(float4*)&cp[j4 * 4] = v;
            }
        }
    }
}

// ---------------------------------------------------------------------------
// Reduce 4 split-K partials: out[i] = sum_s part[s][i]  (float4-wide)
// ---------------------------------------------------------------------------
__global__ void reduce4_kernel(const float* __restrict__ part,
                               float* __restrict__ out)
{
    const int i = (blockIdx.x * 256 + threadIdx.x) * 4;
    const int n = NTOK * 64;
    float4 a = *(const float4*)&part[i];
    float4 b = *(const float4*)&part[i + n];
    float4 c = *(const float4*)&part[i + 2 * n];
    float4 d = *(const float4*)&part[i + 3 * n];
    *(float4*)&out[i] = make_float4(a.x + b.x + c.x + d.x,
                                    a.y + b.y + c.y + d.y,
                                    a.z + b.z + c.z + d.z,
                                    a.w + b.w + c.w + d.w);
}

// ---------------------------------------------------------------------------
// Depthwise causal conv (k=4) + bias + silu.
// Each thread: 4 consecutive tokens x 4 channels (7 float4 loads, 16 outputs).
// ---------------------------------------------------------------------------
__device__ __forceinline__ float getc(float4 v, int k) {
    return k == 0 ? v.x : k == 1 ? v.y : k == 2 ? v.z : v.w;
}
__device__ __forceinline__ float4 silu4(float4 a) {
    a.x = a.x / (1.f + __expf(-a.x));
    a.y = a.y / (1.f + __expf(-a.y));
    a.z = a.z / (1.f + __expf(-a.z));
    a.w = a.w / (1.f + __expf(-a.w));
    return a;
}

__global__ void conv_kernel(const float* __restrict__ xz,
                            const float* __restrict__ cw,
                            const float* __restrict__ cb,
                            float* __restrict__ out)
{
    const int idx = blockIdx.x * blockDim.x + threadIdx.x;   // NTOK/4 * ED/4
    const int e4 = (idx & 255) << 2;
    const int tq = idx >> 8;                 // token quad
    const int tloc = (tq * 4) & (SEQL - 1);  // local pos of first token

    const float4 bias = *(const float4*)&cb[e4];
    const float4 w0 = *(const float4*)&cw[(e4 + 0) * DCONV];
    const float4 w1 = *(const float4*)&cw[(e4 + 1) * DCONV];
    const float4 w2 = *(const float4*)&cw[(e4 + 2) * DCONV];
    const float4 w3 = *(const float4*)&cw[(e4 + 3) * DCONV];

    float4 xv[7];
    #pragma unroll
    for (int s = 0; s < 7; s++) {
        const int tl = tloc - 3 + s;
        xv[s] = (tl >= 0)
            ? *(const float4*)&xz[((size_t)tq * 4 + (s - 3)) * (2 * ED) + e4]
            : make_float4(0.f, 0.f, 0.f, 0.f);
    }

    #pragma unroll
    for (int o = 0; o < 4; o++) {
        float4 acc = bias;
        #pragma unroll
        for (int k = 0; k < DCONV; k++) {
            const float4 v = xv[o + k];
            acc.x = fmaf(getc(w0, k), v.x, acc.x);
            acc.y = fmaf(getc(w1, k), v.y, acc.y);
            acc.z = fmaf(getc(w2, k), v.z, acc.z);
            acc.w = fmaf(getc(w3, k), v.w, acc.w);
        }
        *(float4*)&out[((size_t)tq * 4 + o) * ED + e4] = silu4(acc);
    }
}

// ---------------------------------------------------------------------------
// Selective scan + gating. One warp = 4 channels; 8 lanes/channel, each lane
// owns an adjacent state pair (LDG.64 B/C). 8-token software pipeline.
// ---------------------------------------------------------------------------
__global__ __launch_bounds__(128) void scan_kernel(
    const float* __restrict__ delta,
    const float* __restrict__ xi,
    const float* __restrict__ dbc,
    const float* __restrict__ xz,
    const float* __restrict__ A_log,
    const float* __restrict__ Dp,
    float* __restrict__ y)
{
    const int lane = threadIdx.x & 31;
    const int warp = threadIdx.x >> 5;
    const int ch = lane >> 3;                 // channel within warp
    const int j  = lane & 7;                  // state pair (2j, 2j+1)
    const int c = blockIdx.x * 16 + warp * 4 + ch;
    const int b = c >> 10;
    const int e = c & (ED - 1);

    const float a0 = -__expf(A_log[e * DSTATE + 2 * j]);
    const float a1 = -__expf(A_log[e * DSTATE + 2 * j + 1]);
    const float Dv = Dp[e];

    const float* dptr = delta + (size_t)b * SEQL * ED + e;
    const float* xptr = xi    + (size_t)b * SEQL * ED + e;
    const float* bcp  = dbc   + (size_t)b * SEQL * 64 + DTRANK + 2 * j;
    const float* zptr = xz    + (size_t)b * SEQL * (2 * ED) + ED + e;
    float*       yptr = y     + (size_t)b * SEQL * ED + e;

    constexpr int PF = 8;
    float cdv[PF], cxv[PF], czv[PF];
    float2 cB[PF], cC[PF];
    #pragma unroll
    for (int i = 0; i < PF; i++) {
        cdv[i] = __ldg(&dptr[(size_t)i * ED]);
        cxv[i] = __ldg(&xptr[(size_t)i * ED]);
        czv[i] = __ldg(&zptr[(size_t)i * (2 * ED)]);
        cB[i] = __ldg((const float2*)&bcp[i * 64]);
        cC[i] = __ldg((const float2*)&bcp[i * 64 + DSTATE]);
    }

    float h0 = 0.f, h1 = 0.f;
    for (int t0 = 0; t0 < SEQL; t0 += PF) {
        float ndv[PF], nxv[PF], nzv[PF];
        float2 nB[PF], nC[PF];
        if (t0 + PF < SEQL) {
            #pragma unroll
            for (int i = 0; i < PF; i++) {
                const int t = t0 + PF + i;
                ndv[i] = __ldg(&dptr[(size_t)t * ED]);
                nxv[i] = __ldg(&xptr[(size_t)t * ED]);
                nzv[i] = __ldg(&zptr[(size_t)t * (2 * ED)]);
                nB[i] = __ldg((const float2*)&bcp[t * 64]);
                nC[i] = __ldg((const float2*)&bcp[t * 64 + DSTATE]);
            }
        }
        #pragma unroll
        for (int i = 0; i < PF; i++) {
            const float dA0 = __expf(cdv[i] * a0);
            const float dA1 = __expf(cdv[i] * a1);
            const float u = cdv[i] * cxv[i];
            h0 = fmaf(dA0, h0, u * cB[i].x);
            h1 = fmaf(dA1, h1, u * cB[i].y);
            float p = fmaf(h1, cC[i].y, h0 * cC[i].x);
            p += __shfl_xor_sync(0xffffffffu, p, 4);
            p += __shfl_xor_sync(0xffffffffu, p, 2);
            p += __shfl_xor_sync(0xffffffffu, p, 1);
            if (j == 0) {
                const float zv = czv[i];
                const float silu_z = __fdividef(zv, 1.f + __expf(-zv));
                yptr[(size_t)(t0 + i) * ED] = (p + Dv * cxv[i]) * silu_z;
            }
        }
        #pragma unroll
        for (int i = 0; i < PF; i++) {
            cdv[i] = ndv[i]; cxv[i] = nxv[i]; czv[i] = nzv[i];
            cB[i] = nB[i]; cC[i] = nC[i];
        }
    }
}

// ---------------------------------------------------------------------------
// Host launch
// ---------------------------------------------------------------------------
extern "C" void kernel_launch(void* const* d_in, const int* in_sizes, int n_in,
                              void* d_out, int out_size)
{
    const float* x        = (const float*)d_in[0];
    const float* emb_w    = (const float*)d_in[1];
    const float* emb_b    = (const float*)d_in[2];
    const float* in_w     = (const float*)d_in[3];
    const float* conv_w   = (const float*)d_in[4];
    const float* conv_b   = (const float*)d_in[5];
    const float* xp_w     = (const float*)d_in[6];
    const float* dt_w     = (const float*)d_in[7];
    const float* dt_b     = (const float*)d_in[8];
    const float* A_log    = (const float*)d_in[9];
    const float* Dparam   = (const float*)d_in[10];
    const float* out_w    = (const float*)d_in[11];
    const float* norm_w   = (const float*)d_in[12];
    float* h = (float*)d_out;

    float *xz, *xic, *dbc, *dbcp, *delta, *yb;
    cudaGetSymbolAddress((void**)&xz,    g_xz);
    cudaGetSymbolAddress((void**)&xic,   g_xic);
    cudaGetSymbolAddress((void**)&dbc,   g_dbc);
    cudaGetSymbolAddress((void**)&dbcp,  g_dbcp);
    cudaGetSymbolAddress((void**)&delta, g_delta);
    cudaGetSymbolAddress((void**)&yb,    g_y);

    // Embedding: h = x @ emb_w^T + emb_b  (M=4096, N=512, K=64)
    fgemm<64, true, false, false, false, false>
        <<<dim3(DMODEL / 64, NTOK / 128), 256>>>(
        x, 64, emb_w, 64, emb_b, nullptr, h, DMODEL, 64);

    for (int layer = 0; layer < NLAYERS; layer++) {
        const float* l_in_w   = in_w   + (size_t)layer * 2 * ED * DMODEL;
        const float* l_conv_w = conv_w + (size_t)layer * ED * DCONV;
        const float* l_conv_b = conv_b + (size_t)layer * ED;
        const float* l_xp_w   = xp_w   + (size_t)layer * 64 * ED;
        const float* l_dt_w   = dt_w   + (size_t)layer * ED * DTRANK;
        const float* l_dt_b   = dt_b   + (size_t)layer * ED;
        const float* l_A_log  = A_log  + (size_t)layer * ED * DSTATE;
        const float* l_D      = Dparam + (size_t)layer * ED;
        const float* l_out_w  = out_w  + (size_t)layer * DMODEL * ED;
        const float* l_norm_w = norm_w + (size_t)layer * DMODEL;

        // 1+2. xz = rmsnorm(h) @ in_proj^T, norm fused (M=4096, N=2048, K=512)
        fgemm<128, false, false, false, true, true>
            <<<dim3(2 * ED / 128, NTOK / 128), 256>>>(
            h, DMODEL, l_in_w, DMODEL, nullptr, l_norm_w, xz, 2 * ED, DMODEL);

        // 3. xi = silu(conv(xz[:, :ED]) + cb)
        conv_kernel<<<(NTOK / 4) * (ED / 4) / 256, 256>>>(
            xz, l_conv_w, l_conv_b, xic);

        // 4. dbc = xi @ x_proj^T  (M=4096, N=64, K=1024) — split-K=4
        fgemm<64, false, false, false, false, false, 4>
            <<<dim3(1, NTOK / 128, 4), 256>>>(
            xic, ED, l_xp_w, ED, nullptr, nullptr, dbcp, 64, ED);
        reduce4_kernel<<<(NTOK * 64 / 4) / 256, 256>>>(dbcp, dbc);

        // 5. delta = softplus(dbc[:, :32] @ dt_proj^T + dt_b)  (M=4096, N=1024, K=32)
        fgemm<128, true, false, true, false, false>
            <<<dim3(ED / 128, NTOK / 128), 256>>>(
            dbc, 64, l_dt_w, DTRANK, l_dt_b, nullptr, delta, ED, DTRANK);

        // 6. scan + gating -> y
        scan_kernel<<<(BATCH * ED) / 16, 128>>>(delta, xic, dbc, xz,
                                                l_A_log, l_D, yb);

        // 7. h += y @ out_proj^T  (M=4096, N=512, K=1024)
        fgemm<64, false, true, false, false, false>
            <<<dim3(DMODEL / 64, NTOK / 128), 256>>>(
            yb, ED, l_out_w, ED, nullptr, nullptr, h, DMODEL, ED);
    }
}